// round 4
// baseline (speedup 1.0000x reference)
#include <cuda_runtime.h>

// Problem dims (dataset is fixed)
#define DIN 128
#define DH  256
#define G_MAX 20000

// Persistent scratch for pooled segment sums [G, DH]
__device__ float d_pooled[G_MAX * DH];

// ---------------------------------------------------------------------------
// Kernel 0: zero pooled accumulator
// ---------------------------------------------------------------------------
__global__ void zero_pooled_kernel(int total) {
    int i = blockIdx.x * blockDim.x + threadIdx.x;
    int stride = gridDim.x * blockDim.x;
    for (; i < total; i += stride) d_pooled[i] = 0.0f;
}

// ---------------------------------------------------------------------------
// Kernel 1: fused node MLP (128->256 relu, 256->256 relu) + segmented pool
// Block: 256 threads, tile of 64 nodes.
// smem (floats):
//   A1s [64][132]  input tile (padded)
//   Bs  [32][256]  streamed weight chunk
//   X1s [64][260]  layer-1 output, later reused for layer-2 output
//   gids[64]       graph ids of tile rows (-1 = invalid)
// ---------------------------------------------------------------------------
#define A1_STR 132
#define X1_STR 260
#define SM_A1  0
#define SM_BS  (SM_A1 + 64 * A1_STR)
#define SM_X1  (SM_BS + 32 * DH)
#define SM_GID (SM_X1 + 64 * X1_STR)
#define SM_NODE_FLOATS (SM_GID + 64)

extern "C" __global__ void __launch_bounds__(256, 1)
node_mlp_pool_kernel(const float* __restrict__ h,
                     const int*   __restrict__ graph_ids,
                     const float* __restrict__ W1, const float* __restrict__ b1,
                     const float* __restrict__ W2, const float* __restrict__ b2,
                     int n_atoms)
{
    extern __shared__ float sm[];
    float* A1s = sm + SM_A1;
    float* Bs  = sm + SM_BS;
    float* X1s = sm + SM_X1;
    int*   gids = (int*)(sm + SM_GID);

    const int tid = threadIdx.x;
    const int tx  = tid & 15;          // 0..15 column group
    const int ty  = tid >> 4;          // 0..15 row group
    const int row0 = blockIdx.x * 64;
    const int r0 = ty * 4;             // 4 rows per thread
    const int c0 = tx * 16;            // 16 cols per thread

    // --- load graph ids of this tile ---
    if (tid < 64) {
        int r = row0 + tid;
        gids[tid] = (r < n_atoms) ? graph_ids[r] : -1;
    }

    // --- load A tile (h rows), zero-filled beyond n_atoms ---
    for (int i = tid; i < 64 * (DIN / 4); i += 256) {
        int r  = i >> 5;       // / (DIN/4)=32
        int c4 = i & 31;
        float4 v = make_float4(0.f, 0.f, 0.f, 0.f);
        int gr = row0 + r;
        if (gr < n_atoms)
            v = *(const float4*)(h + (size_t)gr * DIN + c4 * 4);
        *(float4*)(A1s + r * A1_STR + c4 * 4) = v;
    }

    float acc[4][16];
    #pragma unroll
    for (int i = 0; i < 4; i++)
        #pragma unroll
        for (int j = 0; j < 16; j++) acc[i][j] = 0.f;

    // ================= Layer 1: x1 = relu(h @ W1 + b1), K = 128 =============
    for (int kb = 0; kb < DIN; kb += 32) {
        __syncthreads();
        for (int i = tid; i < 32 * (DH / 4); i += 256) {
            int r  = i >> 6;   // / 64
            int c4 = i & 63;
            *(float4*)(Bs + r * DH + c4 * 4) =
                *(const float4*)(W1 + (size_t)(kb + r) * DH + c4 * 4);
        }
        __syncthreads();
        #pragma unroll 8
        for (int kk = 0; kk < 32; kk++) {
            float a0 = A1s[(r0 + 0) * A1_STR + kb + kk];
            float a1 = A1s[(r0 + 1) * A1_STR + kb + kk];
            float a2 = A1s[(r0 + 2) * A1_STR + kb + kk];
            float a3 = A1s[(r0 + 3) * A1_STR + kb + kk];
            const float* brow = Bs + kk * DH + c0;
            float b[16];
            #pragma unroll
            for (int j4 = 0; j4 < 4; j4++) {
                float4 v = *(const float4*)(brow + j4 * 4);
                b[j4*4+0] = v.x; b[j4*4+1] = v.y; b[j4*4+2] = v.z; b[j4*4+3] = v.w;
            }
            #pragma unroll
            for (int j = 0; j < 16; j++) {
                acc[0][j] = fmaf(a0, b[j], acc[0][j]);
                acc[1][j] = fmaf(a1, b[j], acc[1][j]);
                acc[2][j] = fmaf(a2, b[j], acc[2][j]);
                acc[3][j] = fmaf(a3, b[j], acc[3][j]);
            }
        }
    }

    // bias + relu -> X1s
    {
        float bb[16];
        #pragma unroll
        for (int j = 0; j < 16; j++) bb[j] = b1[c0 + j];
        #pragma unroll
        for (int i = 0; i < 4; i++)
            #pragma unroll
            for (int j = 0; j < 16; j++) {
                float v = acc[i][j] + bb[j];
                X1s[(r0 + i) * X1_STR + c0 + j] = v > 0.f ? v : 0.f;
                acc[i][j] = 0.f;
            }
    }

    // ================= Layer 2: x2 = relu(x1 @ W2 + b2), K = 256 ============
    for (int kb = 0; kb < DH; kb += 32) {
        __syncthreads();   // also orders X1s writes before first read
        for (int i = tid; i < 32 * (DH / 4); i += 256) {
            int r  = i >> 6;
            int c4 = i & 63;
            *(float4*)(Bs + r * DH + c4 * 4) =
                *(const float4*)(W2 + (size_t)(kb + r) * DH + c4 * 4);
        }
        __syncthreads();
        #pragma unroll 8
        for (int kk = 0; kk < 32; kk++) {
            float a0 = X1s[(r0 + 0) * X1_STR + kb + kk];
            float a1 = X1s[(r0 + 1) * X1_STR + kb + kk];
            float a2 = X1s[(r0 + 2) * X1_STR + kb + kk];
            float a3 = X1s[(r0 + 3) * X1_STR + kb + kk];
            const float* brow = Bs + kk * DH + c0;
            float b[16];
            #pragma unroll
            for (int j4 = 0; j4 < 4; j4++) {
                float4 v = *(const float4*)(brow + j4 * 4);
                b[j4*4+0] = v.x; b[j4*4+1] = v.y; b[j4*4+2] = v.z; b[j4*4+3] = v.w;
            }
            #pragma unroll
            for (int j = 0; j < 16; j++) {
                acc[0][j] = fmaf(a0, b[j], acc[0][j]);
                acc[1][j] = fmaf(a1, b[j], acc[1][j]);
                acc[2][j] = fmaf(a2, b[j], acc[2][j]);
                acc[3][j] = fmaf(a3, b[j], acc[3][j]);
            }
        }
    }

    // bias + relu -> reuse X1s as X2 storage
    __syncthreads();   // all layer-2 reads of X1s done
    {
        float bb[16];
        #pragma unroll
        for (int j = 0; j < 16; j++) bb[j] = b2[c0 + j];
        #pragma unroll
        for (int i = 0; i < 4; i++)
            #pragma unroll
            for (int j = 0; j < 16; j++) {
                float v = acc[i][j] + bb[j];
                X1s[(r0 + i) * X1_STR + c0 + j] = v > 0.f ? v : 0.f;
            }
    }
    __syncthreads();

    // ============== block-local segmented sum, then atomics =================
    // thread tid owns column tid; walk 64 sorted rows, flush on id change
    {
        const int c = tid;
        int cur = -1;
        float s = 0.f;
        #pragma unroll 8
        for (int r = 0; r < 64; r++) {
            int g = gids[r];
            if (g != cur) {
                if (cur >= 0) atomicAdd(&d_pooled[(size_t)cur * DH + c], s);
                cur = g;
                s = 0.f;
            }
            if (g >= 0) s += X1s[r * X1_STR + c];
        }
        if (cur >= 0) atomicAdd(&d_pooled[(size_t)cur * DH + c], s);
    }
}

// ---------------------------------------------------------------------------
// Kernel 2: graph MLP  y = relu(pooled @ Wg1 + bg1); out = y @ Wg2 + bg2
// Block: 256 threads, tile of 64 graphs.
// smem: Ps[64][260] (reused for y), Bs[32][256], wsv[256]
// ---------------------------------------------------------------------------
#define GM_PS  0
#define GM_BS  (GM_PS + 64 * X1_STR)
#define GM_WS  (GM_BS + 32 * DH)
#define SM_GRAPH_FLOATS (GM_WS + DH)

extern "C" __global__ void __launch_bounds__(256, 1)
graph_mlp_kernel(const float* __restrict__ Wg1, const float* __restrict__ bg1,
                 const float* __restrict__ Wg2, const float* __restrict__ bg2,
                 float* __restrict__ out, int num_graphs)
{
    extern __shared__ float sm[];
    float* Ps  = sm + GM_PS;
    float* Bs  = sm + GM_BS;
    float* wsv = sm + GM_WS;

    const int tid = threadIdx.x;
    const int tx  = tid & 15;
    const int ty  = tid >> 4;
    const int g0  = blockIdx.x * 64;
    const int r0  = ty * 4;
    const int c0  = tx * 16;

    // load pooled tile (zero-fill beyond num_graphs)
    for (int i = tid; i < 64 * (DH / 4); i += 256) {
        int r  = i >> 6;
        int c4 = i & 63;
        float4 v = make_float4(0.f, 0.f, 0.f, 0.f);
        if (g0 + r < num_graphs)
            v = *(const float4*)(d_pooled + (size_t)(g0 + r) * DH + c4 * 4);
        *(float4*)(Ps + r * X1_STR + c4 * 4) = v;
    }
    if (tid < DH) wsv[tid] = Wg2[tid];

    float acc[4][16];
    #pragma unroll
    for (int i = 0; i < 4; i++)
        #pragma unroll
        for (int j = 0; j < 16; j++) acc[i][j] = 0.f;

    for (int kb = 0; kb < DH; kb += 32) {
        __syncthreads();
        for (int i = tid; i < 32 * (DH / 4); i += 256) {
            int r  = i >> 6;
            int c4 = i & 63;
            *(float4*)(Bs + r * DH + c4 * 4) =
                *(const float4*)(Wg1 + (size_t)(kb + r) * DH + c4 * 4);
        }
        __syncthreads();
        #pragma unroll 8
        for (int kk = 0; kk < 32; kk++) {
            float a0 = Ps[(r0 + 0) * X1_STR + kb + kk];
            float a1 = Ps[(r0 + 1) * X1_STR + kb + kk];
            float a2 = Ps[(r0 + 2) * X1_STR + kb + kk];
            float a3 = Ps[(r0 + 3) * X1_STR + kb + kk];
            const float* brow = Bs + kk * DH + c0;
            float b[16];
            #pragma unroll
            for (int j4 = 0; j4 < 4; j4++) {
                float4 v = *(const float4*)(brow + j4 * 4);
                b[j4*4+0] = v.x; b[j4*4+1] = v.y; b[j4*4+2] = v.z; b[j4*4+3] = v.w;
            }
            #pragma unroll
            for (int j = 0; j < 16; j++) {
                acc[0][j] = fmaf(a0, b[j], acc[0][j]);
                acc[1][j] = fmaf(a1, b[j], acc[1][j]);
                acc[2][j] = fmaf(a2, b[j], acc[2][j]);
                acc[3][j] = fmaf(a3, b[j], acc[3][j]);
            }
        }
    }

    // bias + relu -> write y back into Ps
    __syncthreads();
    {
        float bb[16];
        #pragma unroll
        for (int j = 0; j < 16; j++) bb[j] = bg1[c0 + j];
        #pragma unroll
        for (int i = 0; i < 4; i++)
            #pragma unroll
            for (int j = 0; j < 16; j++) {
                float v = acc[i][j] + bb[j];
                Ps[(r0 + i) * X1_STR + c0 + j] = v > 0.f ? v : 0.f;
            }
    }
    __syncthreads();

    // final 256 -> 1 dot product per graph; warp w handles rows 8w..8w+7
    {
        const int w    = tid >> 5;
        const int lane = tid & 31;
        const float bg2v = bg2[0];
        #pragma unroll
        for (int rr = 0; rr < 8; rr++) {
            int r = w * 8 + rr;
            float s = 0.f;
            #pragma unroll
            for (int t = 0; t < 8; t++)
                s += Ps[r * X1_STR + lane + 32 * t] * wsv[lane + 32 * t];
            #pragma unroll
            for (int off = 16; off; off >>= 1)
                s += __shfl_xor_sync(0xffffffffu, s, off);
            if (lane == 0 && (g0 + r) < num_graphs)
                out[g0 + r] = s + bg2v;
        }
    }
}

// ---------------------------------------------------------------------------
extern "C" void kernel_launch(void* const* d_in, const int* in_sizes, int n_in,
                              void* d_out, int out_size) {
    // Input layout per reference setup_inputs():
    //   h, graph_ids, [num_graphs scalar?], W1, b1, W2, b2, Wg1, bg1, Wg2, bg2
    // Be robust to whether the num_graphs scalar appears as an input buffer.
    const float* h         = (const float*)d_in[0];
    const int*   graph_ids = (const int*)  d_in[1];
    const int base = (n_in >= 11) ? 3 : 2;   // skip scalar slot if present
    const float* W1  = (const float*)d_in[base + 0];
    const float* b1  = (const float*)d_in[base + 1];
    const float* W2  = (const float*)d_in[base + 2];
    const float* b2  = (const float*)d_in[base + 3];
    const float* Wg1 = (const float*)d_in[base + 4];
    const float* bg1 = (const float*)d_in[base + 5];
    const float* Wg2 = (const float*)d_in[base + 6];
    const float* bg2 = (const float*)d_in[base + 7];
    float* out = (float*)d_out;

    const int n_atoms = in_sizes[0] / DIN;
    const int G       = out_size;          // D_OUT = 1

    static bool attrs_set = false;
    if (!attrs_set) {
        cudaFuncSetAttribute(node_mlp_pool_kernel,
                             cudaFuncAttributeMaxDynamicSharedMemorySize,
                             SM_NODE_FLOATS * (int)sizeof(float));
        cudaFuncSetAttribute(graph_mlp_kernel,
                             cudaFuncAttributeMaxDynamicSharedMemorySize,
                             SM_GRAPH_FLOATS * (int)sizeof(float));
        attrs_set = true;
    }

    zero_pooled_kernel<<<512, 256>>>(G * DH);

    int nblocks = (n_atoms + 63) / 64;
    node_mlp_pool_kernel<<<nblocks, 256, SM_NODE_FLOATS * sizeof(float)>>>(
        h, graph_ids, W1, b1, W2, b2, n_atoms);

    int gblocks = (G + 63) / 64;
    graph_mlp_kernel<<<gblocks, 256, SM_GRAPH_FLOATS * sizeof(float)>>>(
        Wg1, bg1, Wg2, bg2, out, G);
}

// round 8
// speedup vs baseline: 5.1012x; 5.1012x over previous
#include <cuda_runtime.h>
#include <cuda_bf16.h>
#include <cstdint>

#define DIN 128
#define DH  256
#define G_MAX 20000
#define TILE_M 128

// ---------------------------------------------------------------------------
// Persistent scratch
// ---------------------------------------------------------------------------
__device__ float d_pooled[G_MAX * DH];
// W1^T hi/lo, smem-image layout [n=256][k pad 136] bf16 (hi then lo, contiguous)
__device__ __align__(16) __nv_bfloat16 d_W1t[2][256 * 136];
// W2^T hi/lo in 4 K-chunks of 64: [part][chunk][n=256][kk pad 72]
__device__ __align__(16) __nv_bfloat16 d_W2t[2][4][256 * 72];

// ---------------------------------------------------------------------------
// helpers
// ---------------------------------------------------------------------------
__device__ __forceinline__ uint32_t smem_to_u32(const void* p) {
    uint32_t a;
    asm("{ .reg .u64 t; cvta.to.shared.u64 t, %1; cvt.u32.u64 %0, t; }" : "=r"(a) : "l"(p));
    return a;
}
__device__ __forceinline__ uint32_t lds32(uint32_t a) {
    uint32_t v;
    asm volatile("ld.shared.b32 %0, [%1];" : "=r"(v) : "r"(a));
    return v;
}
__device__ __forceinline__ void sts32(uint32_t a, uint32_t v) {
    asm volatile("st.shared.b32 [%0], %1;" :: "r"(a), "r"(v));
}
// m16n8k16 row.col f32.bf16.bf16.f32
__device__ __forceinline__ void mma_bf16(float* d, uint32_t a0, uint32_t a1, uint32_t a2,
                                         uint32_t a3, uint32_t b0, uint32_t b1) {
    asm volatile(
        "mma.sync.aligned.m16n8k16.row.col.f32.bf16.bf16.f32 "
        "{%0,%1,%2,%3}, {%4,%5,%6,%7}, {%8,%9}, {%0,%1,%2,%3};"
        : "+f"(d[0]), "+f"(d[1]), "+f"(d[2]), "+f"(d[3])
        : "r"(a0), "r"(a1), "r"(a2), "r"(a3), "r"(b0), "r"(b1));
}
__device__ __forceinline__ uint32_t pack_hi(float v0, float v1, uint32_t& lo_out) {
    __nv_bfloat16 h0 = __float2bfloat16(v0), h1 = __float2bfloat16(v1);
    __nv_bfloat16 l0 = __float2bfloat16(v0 - __bfloat162float(h0));
    __nv_bfloat16 l1 = __float2bfloat16(v1 - __bfloat162float(h1));
    lo_out = (uint32_t)__bfloat16_as_ushort(l0) | ((uint32_t)__bfloat16_as_ushort(l1) << 16);
    return (uint32_t)__bfloat16_as_ushort(h0) | ((uint32_t)__bfloat16_as_ushort(h1) << 16);
}

// ---------------------------------------------------------------------------
// Kernel 0: zero pooled accumulator
// ---------------------------------------------------------------------------
__global__ void zero_pooled_kernel(int total) {
    int i = blockIdx.x * blockDim.x + threadIdx.x;
    int stride = gridDim.x * blockDim.x;
    for (; i < total; i += stride) d_pooled[i] = 0.0f;
}

// ---------------------------------------------------------------------------
// Kernel P: bake W1^T / W2^T into bf16 hi/lo smem-image layouts
// ---------------------------------------------------------------------------
__global__ void prep_kernel(const float* __restrict__ W1, const float* __restrict__ W2) {
    int idx = blockIdx.x * blockDim.x + threadIdx.x;
    if (idx < DIN * DH) {                  // W1 [k=128][n=256]
        int k = idx / DH, n = idx % DH;
        float v = W1[idx];
        __nv_bfloat16 hi = __float2bfloat16(v);
        __nv_bfloat16 lo = __float2bfloat16(v - __bfloat162float(hi));
        d_W1t[0][n * 136 + k] = hi;
        d_W1t[1][n * 136 + k] = lo;
    } else if (idx < DIN * DH + DH * DH) { // W2 [k=256][n=256]
        int i2 = idx - DIN * DH;
        int k = i2 / DH, n = i2 % DH;
        float v = W2[i2];
        __nv_bfloat16 hi = __float2bfloat16(v);
        __nv_bfloat16 lo = __float2bfloat16(v - __bfloat162float(hi));
        int chunk = k >> 6, kk = k & 63;
        d_W2t[0][chunk][n * 72 + kk] = hi;
        d_W2t[1][chunk][n * 72 + kk] = lo;
    }
}

// ---------------------------------------------------------------------------
// Kernel 1: fused node MLP via mma.sync split-bf16 + segmented pool
// 256 threads (8 warps), 128-node tile, warp w owns rows [16w,16w+16), N=256.
// smem (bytes):
//   phase1: A1hi[128][136]bf16 @0 (34816), A1lo @34816,
//           W1hi[256][136] @69632 (69632), W1lo @139264   -> 208896
//   phase2: A2hi[128][264] @0 (67584), A2lo @67584,
//           W2Chi[256][72] @135168 (36864), W2Clo @172032 -> 208896
//   epi2 :  X2 fp32 [128][264] @0 (135168)   (after all mma reads)
//   aux  :  b1s @208896, b2s @209920, gids @210944        -> 211456 total
// ---------------------------------------------------------------------------
#define SA1_HI 0
#define SA1_LO 34816
#define SW1_HI 69632
#define SW1_LO 139264
#define SA2_HI 0
#define SA2_LO 67584
#define SW2_HI 135168
#define SW2_LO 172032
#define SX2    0
#define SO_B1S 208896
#define SO_B2S 209920
#define SO_GID 210944
#define NODE_SMEM_BYTES 211456

extern "C" __global__ void __launch_bounds__(256, 1)
node_kernel(const float* __restrict__ h, const int* __restrict__ graph_ids,
            const float* __restrict__ b1, const float* __restrict__ b2, int n_atoms)
{
    extern __shared__ unsigned char sm[];
    const uint32_t smb = smem_to_u32(sm);
    const int tid = threadIdx.x;
    const int w   = tid >> 5;
    const int l   = tid & 31;
    const int q   = l >> 2;          // 0..7
    const int m   = l & 3;           // 0..3
    const int R   = w * 16 + q;      // fragment row (and R+8)
    const int row0 = blockIdx.x * TILE_M;

    float* b1s = (float*)(sm + SO_B1S);
    float* b2s = (float*)(sm + SO_B2S);
    int*   gids = (int*)(sm + SO_GID);

    b1s[tid] = b1[tid];
    b2s[tid] = b2[tid];
    if (tid < TILE_M) {
        int r = row0 + tid;
        gids[tid] = (r < n_atoms) ? graph_ids[r] : -1;
    }

    // ---- A1: load h tile, split to bf16 hi/lo, [r][k] stride 136 ----
    #pragma unroll 4
    for (int it = 0; it < 16; it++) {
        int idx = tid + it * 256;          // 128 rows x 32 float4
        int r = idx >> 5, c = (idx & 31) * 4;
        float4 v = make_float4(0.f, 0.f, 0.f, 0.f);
        if (row0 + r < n_atoms)
            v = *(const float4*)(h + (size_t)(row0 + r) * DIN + c);
        uint32_t lo0, lo1;
        uint32_t hi0 = pack_hi(v.x, v.y, lo0);
        uint32_t hi1 = pack_hi(v.z, v.w, lo1);
        uint32_t off = (uint32_t)(r * 136 + c) * 2;
        *(uint2*)(sm + SA1_HI + off) = make_uint2(hi0, hi1);
        *(uint2*)(sm + SA1_LO + off) = make_uint2(lo0, lo1);
    }
    // ---- copy W1 image (hi+lo contiguous, 139264 B = 8704 float4) ----
    {
        const float4* src = (const float4*)&d_W1t[0][0];
        float4* dst = (float4*)(sm + SW1_HI);
        #pragma unroll 8
        for (int it = 0; it < 34; it++)
            dst[tid + it * 256] = src[tid + it * 256];
    }
    __syncthreads();

    float acc[128];
    #pragma unroll
    for (int i = 0; i < 128; i++) acc[i] = 0.f;

    // ================= Layer 1: K=128, 8 k-steps =================
    for (int ks = 0; ks < 8; ks++) {
        uint32_t ao = smb + (uint32_t)((R * 136 + ks * 16 + m * 2) * 2);
        uint32_t aH0 = lds32(ao + SA1_HI),        aH1 = lds32(ao + SA1_HI + 2176);
        uint32_t aH2 = lds32(ao + SA1_HI + 16),   aH3 = lds32(ao + SA1_HI + 2192);
        uint32_t aL0 = lds32(ao + SA1_LO),        aL1 = lds32(ao + SA1_LO + 2176);
        uint32_t aL2 = lds32(ao + SA1_LO + 16),   aL3 = lds32(ao + SA1_LO + 2192);
        #pragma unroll
        for (int nt = 0; nt < 32; nt++) {
            uint32_t bo = smb + (uint32_t)(((nt * 8 + q) * 136 + ks * 16 + m * 2) * 2);
            uint32_t bH0 = lds32(bo + SW1_HI), bH1 = lds32(bo + SW1_HI + 16);
            uint32_t bL0 = lds32(bo + SW1_LO), bL1 = lds32(bo + SW1_LO + 16);
            float* d = acc + nt * 4;
            mma_bf16(d, aH0, aH1, aH2, aH3, bH0, bH1);
            mma_bf16(d, aL0, aL1, aL2, aL3, bH0, bH1);
            mma_bf16(d, aH0, aH1, aH2, aH3, bL0, bL1);
        }
    }
    __syncthreads();   // all layer-1 mma reads of A1/W1 done before A2 overwrites

    // ===== Epilogue 1: bias+relu, re-split -> A2 [r][c] stride 264 =====
    #pragma unroll
    for (int nt = 0; nt < 32; nt++) {
        int c = nt * 8 + m * 2;
        float v0 = fmaxf(acc[nt * 4 + 0] + b1s[c],     0.f);
        float v1 = fmaxf(acc[nt * 4 + 1] + b1s[c + 1], 0.f);
        float v2 = fmaxf(acc[nt * 4 + 2] + b1s[c],     0.f);
        float v3 = fmaxf(acc[nt * 4 + 3] + b1s[c + 1], 0.f);
        uint32_t lo01, lo23;
        uint32_t hi01 = pack_hi(v0, v1, lo01);
        uint32_t hi23 = pack_hi(v2, v3, lo23);
        uint32_t off = (uint32_t)((R * 264 + c) * 2);
        sts32(smb + SA2_HI + off, hi01);
        sts32(smb + SA2_HI + off + 4224, hi23);   // row +8
        sts32(smb + SA2_LO + off, lo01);
        sts32(smb + SA2_LO + off + 4224, lo23);
        acc[nt * 4 + 0] = 0.f; acc[nt * 4 + 1] = 0.f;
        acc[nt * 4 + 2] = 0.f; acc[nt * 4 + 3] = 0.f;
    }
    __syncthreads();

    // ================= Layer 2: K=256 in 4 chunks of 64 =================
    for (int ch = 0; ch < 4; ch++) {
        // stream W2 chunk (hi and lo, 2304 float4 each)
        {
            const float4* sh = (const float4*)&d_W2t[0][ch][0];
            const float4* sl = (const float4*)&d_W2t[1][ch][0];
            float4* dh = (float4*)(sm + SW2_HI);
            float4* dl = (float4*)(sm + SW2_LO);
            #pragma unroll
            for (int it = 0; it < 9; it++) {
                dh[tid + it * 256] = sh[tid + it * 256];
                dl[tid + it * 256] = sl[tid + it * 256];
            }
        }
        __syncthreads();
        for (int ks = 0; ks < 4; ks++) {
            uint32_t ao = smb + (uint32_t)((R * 264 + ch * 64 + ks * 16 + m * 2) * 2);
            uint32_t aH0 = lds32(ao + SA2_HI),      aH1 = lds32(ao + SA2_HI + 4224);
            uint32_t aH2 = lds32(ao + SA2_HI + 16), aH3 = lds32(ao + SA2_HI + 4240);
            uint32_t aL0 = lds32(ao + SA2_LO),      aL1 = lds32(ao + SA2_LO + 4224);
            uint32_t aL2 = lds32(ao + SA2_LO + 16), aL3 = lds32(ao + SA2_LO + 4240);
            #pragma unroll
            for (int nt = 0; nt < 32; nt++) {
                uint32_t bo = smb + (uint32_t)(((nt * 8 + q) * 72 + ks * 16 + m * 2) * 2);
                uint32_t bH0 = lds32(bo + SW2_HI), bH1 = lds32(bo + SW2_HI + 16);
                uint32_t bL0 = lds32(bo + SW2_LO), bL1 = lds32(bo + SW2_LO + 16);
                float* d = acc + nt * 4;
                mma_bf16(d, aH0, aH1, aH2, aH3, bH0, bH1);
                mma_bf16(d, aL0, aL1, aL2, aL3, bH0, bH1);
                mma_bf16(d, aH0, aH1, aH2, aH3, bL0, bL1);
            }
        }
        __syncthreads();   // chunk consumed before next overwrite / before X2 alias
    }

    // ===== Epilogue 2: bias+relu -> X2 fp32 [r][264] (aliases A2; mma done) =====
    {
        float* X2 = (float*)(sm + SX2);
        #pragma unroll
        for (int nt = 0; nt < 32; nt++) {
            int c = nt * 8 + m * 2;
            X2[R * 264 + c]             = fmaxf(acc[nt * 4 + 0] + b2s[c],     0.f);
            X2[R * 264 + c + 1]         = fmaxf(acc[nt * 4 + 1] + b2s[c + 1], 0.f);
            X2[(R + 8) * 264 + c]       = fmaxf(acc[nt * 4 + 2] + b2s[c],     0.f);
            X2[(R + 8) * 264 + c + 1]   = fmaxf(acc[nt * 4 + 3] + b2s[c + 1], 0.f);
        }
    }
    __syncthreads();

    // ===== Block-local segmented sum over sorted gids, then atomics =====
    {
        const int col = tid;                 // one of 256 feature columns
        const float* X2 = (const float*)(sm + SX2);
        int cur = -1;
        float s = 0.f;
        #pragma unroll 8
        for (int r = 0; r < TILE_M; r++) {
            int g = gids[r];
            if (g != cur) {
                if (cur >= 0) atomicAdd(&d_pooled[(size_t)cur * DH + col], s);
                cur = g;
                s = 0.f;
            }
            if (g >= 0) s += X2[r * 264 + col];
        }
        if (cur >= 0) atomicAdd(&d_pooled[(size_t)cur * DH + col], s);
    }
}

// ---------------------------------------------------------------------------
// Kernel 2: graph MLP (SIMT, known-good)
// ---------------------------------------------------------------------------
#define GQ_STR 260
#define GM_PS  0
#define GM_BS  (GM_PS + 64 * GQ_STR)
#define GM_WS  (GM_BS + 32 * DH)
#define SM_GRAPH_FLOATS (GM_WS + DH)

extern "C" __global__ void __launch_bounds__(256, 1)
graph_mlp_kernel(const float* __restrict__ Wg1, const float* __restrict__ bg1,
                 const float* __restrict__ Wg2, const float* __restrict__ bg2,
                 float* __restrict__ out, int num_graphs)
{
    extern __shared__ float smf[];
    float* Ps  = smf + GM_PS;
    float* Bs  = smf + GM_BS;
    float* wsv = smf + GM_WS;

    const int tid = threadIdx.x;
    const int tx  = tid & 15;
    const int ty  = tid >> 4;
    const int g0  = blockIdx.x * 64;
    const int r0  = ty * 4;
    const int c0  = tx * 16;

    for (int i = tid; i < 64 * (DH / 4); i += 256) {
        int r  = i >> 6;
        int c4 = i & 63;
        float4 v = make_float4(0.f, 0.f, 0.f, 0.f);
        if (g0 + r < num_graphs)
            v = *(const float4*)(d_pooled + (size_t)(g0 + r) * DH + c4 * 4);
        *(float4*)(Ps + r * GQ_STR + c4 * 4) = v;
    }
    if (tid < DH) wsv[tid] = Wg2[tid];

    float acc[4][16];
    #pragma unroll
    for (int i = 0; i < 4; i++)
        #pragma unroll
        for (int j = 0; j < 16; j++) acc[i][j] = 0.f;

    for (int kb = 0; kb < DH; kb += 32) {
        __syncthreads();
        for (int i = tid; i < 32 * (DH / 4); i += 256) {
            int r  = i >> 6;
            int c4 = i & 63;
            *(float4*)(Bs + r * DH + c4 * 4) =
                *(const float4*)(Wg1 + (size_t)(kb + r) * DH + c4 * 4);
        }
        __syncthreads();
        #pragma unroll 8
        for (int kk = 0; kk < 32; kk++) {
            float a0 = Ps[(r0 + 0) * GQ_STR + kb + kk];
            float a1 = Ps[(r0 + 1) * GQ_STR + kb + kk];
            float a2 = Ps[(r0 + 2) * GQ_STR + kb + kk];
            float a3 = Ps[(r0 + 3) * GQ_STR + kb + kk];
            const float* brow = Bs + kk * DH + c0;
            float b[16];
            #pragma unroll
            for (int j4 = 0; j4 < 4; j4++) {
                float4 v = *(const float4*)(brow + j4 * 4);
                b[j4*4+0] = v.x; b[j4*4+1] = v.y; b[j4*4+2] = v.z; b[j4*4+3] = v.w;
            }
            #pragma unroll
            for (int j = 0; j < 16; j++) {
                acc[0][j] = fmaf(a0, b[j], acc[0][j]);
                acc[1][j] = fmaf(a1, b[j], acc[1][j]);
                acc[2][j] = fmaf(a2, b[j], acc[2][j]);
                acc[3][j] = fmaf(a3, b[j], acc[3][j]);
            }
        }
    }

    __syncthreads();
    {
        float bb[16];
        #pragma unroll
        for (int j = 0; j < 16; j++) bb[j] = bg1[c0 + j];
        #pragma unroll
        for (int i = 0; i < 4; i++)
            #pragma unroll
            for (int j = 0; j < 16; j++) {
                float v = acc[i][j] + bb[j];
                Ps[(r0 + i) * GQ_STR + c0 + j] = v > 0.f ? v : 0.f;
            }
    }
    __syncthreads();

    {
        const int wr   = tid >> 5;
        const int lane = tid & 31;
        const float bg2v = bg2[0];
        #pragma unroll
        for (int rr = 0; rr < 8; rr++) {
            int r = wr * 8 + rr;
            float s = 0.f;
            #pragma unroll
            for (int t = 0; t < 8; t++)
                s += Ps[r * GQ_STR + lane + 32 * t] * wsv[lane + 32 * t];
            #pragma unroll
            for (int off = 16; off; off >>= 1)
                s += __shfl_xor_sync(0xffffffffu, s, off);
            if (lane == 0 && (g0 + r) < num_graphs)
                out[g0 + r] = s + bg2v;
        }
    }
}

// ---------------------------------------------------------------------------
extern "C" void kernel_launch(void* const* d_in, const int* in_sizes, int n_in,
                              void* d_out, int out_size) {
    const float* h         = (const float*)d_in[0];
    const int*   graph_ids = (const int*)  d_in[1];
    const int base = (n_in >= 11) ? 3 : 2;   // skip num_graphs scalar slot if present
    const float* W1  = (const float*)d_in[base + 0];
    const float* b1  = (const float*)d_in[base + 1];
    const float* W2  = (const float*)d_in[base + 2];
    const float* b2  = (const float*)d_in[base + 3];
    const float* Wg1 = (const float*)d_in[base + 4];
    const float* bg1 = (const float*)d_in[base + 5];
    const float* Wg2 = (const float*)d_in[base + 6];
    const float* bg2 = (const float*)d_in[base + 7];
    float* out = (float*)d_out;

    const int n_atoms = in_sizes[0] / DIN;
    const int G       = out_size;            // D_OUT = 1

    static bool attrs_set = false;
    if (!attrs_set) {
        cudaFuncSetAttribute(node_kernel,
                             cudaFuncAttributeMaxDynamicSharedMemorySize, NODE_SMEM_BYTES);
        cudaFuncSetAttribute(graph_mlp_kernel,
                             cudaFuncAttributeMaxDynamicSharedMemorySize,
                             SM_GRAPH_FLOATS * (int)sizeof(float));
        attrs_set = true;
    }

    prep_kernel<<<(DIN * DH + DH * DH + 255) / 256, 256>>>(W1, W2);
    zero_pooled_kernel<<<512, 256>>>(G * DH);

    int nblocks = (n_atoms + TILE_M - 1) / TILE_M;
    node_kernel<<<nblocks, 256, NODE_SMEM_BYTES>>>(h, graph_ids, b1, b2, n_atoms);

    int gblocks = (G + 63) / 64;
    graph_mlp_kernel<<<gblocks, 256, SM_GRAPH_FLOATS * sizeof(float)>>>(
        Wg1, bg1, Wg2, bg2, out, G);
}

// round 9
// speedup vs baseline: 5.9350x; 1.1634x over previous
#include <cuda_runtime.h>
#include <cuda_bf16.h>
#include <cstdint>

#define DIN 128
#define DH  256
#define G_MAX 20000
#define TILE_M 128

// ---------------------------------------------------------------------------
// Persistent scratch
// ---------------------------------------------------------------------------
__device__ float d_pooled[G_MAX * DH];
// W1^T hi/lo, smem-image [n=256][k pad 136] bf16 (hi block then lo block)
__device__ __align__(16) __nv_bfloat16 d_W1t[2][256 * 136];
// W2^T hi/lo in 8 K-chunks of 32: [part][chunk][n=256][kk pad 40]
__device__ __align__(16) __nv_bfloat16 d_W2t[2][8][256 * 40];
// Wg1^T hi/lo, same chunking
__device__ __align__(16) __nv_bfloat16 d_Wg1t[2][8][256 * 40];

// ---------------------------------------------------------------------------
// helpers
// ---------------------------------------------------------------------------
__device__ __forceinline__ uint32_t smem_to_u32(const void* p) {
    uint32_t a;
    asm("{ .reg .u64 t; cvta.to.shared.u64 t, %1; cvt.u32.u64 %0, t; }" : "=r"(a) : "l"(p));
    return a;
}
__device__ __forceinline__ uint32_t lds32(uint32_t a) {
    uint32_t v;
    asm volatile("ld.shared.b32 %0, [%1];" : "=r"(v) : "r"(a));
    return v;
}
__device__ __forceinline__ void sts32(uint32_t a, uint32_t v) {
    asm volatile("st.shared.b32 [%0], %1;" :: "r"(a), "r"(v));
}
__device__ __forceinline__ void cp16(uint32_t s, const void* g) {
    asm volatile("cp.async.ca.shared.global [%0], [%1], 16;" :: "r"(s), "l"(g));
}
#define CP_COMMIT() asm volatile("cp.async.commit_group;" ::: "memory")
#define CP_WAIT0()  asm volatile("cp.async.wait_group 0;" ::: "memory")
#define CP_WAIT1()  asm volatile("cp.async.wait_group 1;" ::: "memory")

// m16n8k16 row.col f32.bf16.bf16.f32
__device__ __forceinline__ void mma_bf16(float* d, uint32_t a0, uint32_t a1, uint32_t a2,
                                         uint32_t a3, uint32_t b0, uint32_t b1) {
    asm volatile(
        "mma.sync.aligned.m16n8k16.row.col.f32.bf16.bf16.f32 "
        "{%0,%1,%2,%3}, {%4,%5,%6,%7}, {%8,%9}, {%0,%1,%2,%3};"
        : "+f"(d[0]), "+f"(d[1]), "+f"(d[2]), "+f"(d[3])
        : "r"(a0), "r"(a1), "r"(a2), "r"(a3), "r"(b0), "r"(b1));
}
__device__ __forceinline__ uint32_t pack_hi(float v0, float v1, uint32_t& lo_out) {
    __nv_bfloat16 h0 = __float2bfloat16(v0), h1 = __float2bfloat16(v1);
    __nv_bfloat16 l0 = __float2bfloat16(v0 - __bfloat162float(h0));
    __nv_bfloat16 l1 = __float2bfloat16(v1 - __bfloat162float(h1));
    lo_out = (uint32_t)__bfloat16_as_ushort(l0) | ((uint32_t)__bfloat16_as_ushort(l1) << 16);
    return (uint32_t)__bfloat16_as_ushort(h0) | ((uint32_t)__bfloat16_as_ushort(h1) << 16);
}

// ---------------------------------------------------------------------------
// Kernel 0: zero pooled accumulator
// ---------------------------------------------------------------------------
__global__ void zero_pooled_kernel(int total) {
    int i = blockIdx.x * blockDim.x + threadIdx.x;
    int stride = gridDim.x * blockDim.x;
    for (; i < total; i += stride) d_pooled[i] = 0.0f;
}

// ---------------------------------------------------------------------------
// Kernel P: bake W1^T / W2^T / Wg1^T into bf16 hi/lo images
// ---------------------------------------------------------------------------
__global__ void prep_kernel(const float* __restrict__ W1, const float* __restrict__ W2,
                            const float* __restrict__ Wg1) {
    int idx = blockIdx.x * blockDim.x + threadIdx.x;
    if (idx < DIN * DH) {                          // W1 [k=128][n=256]
        int k = idx / DH, n = idx % DH;
        float v = W1[idx];
        __nv_bfloat16 hi = __float2bfloat16(v);
        __nv_bfloat16 lo = __float2bfloat16(v - __bfloat162float(hi));
        d_W1t[0][n * 136 + k] = hi;
        d_W1t[1][n * 136 + k] = lo;
    } else if (idx < DIN * DH + DH * DH) {         // W2 [k=256][n=256]
        int i2 = idx - DIN * DH;
        int k = i2 / DH, n = i2 % DH;
        float v = W2[i2];
        __nv_bfloat16 hi = __float2bfloat16(v);
        __nv_bfloat16 lo = __float2bfloat16(v - __bfloat162float(hi));
        d_W2t[0][k >> 5][n * 40 + (k & 31)] = hi;
        d_W2t[1][k >> 5][n * 40 + (k & 31)] = lo;
    } else if (idx < DIN * DH + 2 * DH * DH) {     // Wg1 [k=256][n=256]
        int i2 = idx - DIN * DH - DH * DH;
        int k = i2 / DH, n = i2 % DH;
        float v = Wg1[i2];
        __nv_bfloat16 hi = __float2bfloat16(v);
        __nv_bfloat16 lo = __float2bfloat16(v - __bfloat162float(hi));
        d_Wg1t[0][k >> 5][n * 40 + (k & 31)] = hi;
        d_Wg1t[1][k >> 5][n * 40 + (k & 31)] = lo;
    }
}

// ---------------------------------------------------------------------------
// Kernel 1: fused node MLP via mma.sync split-bf16 + segmented pool
// 256 threads (8 warps, grid 2M x 4N, 64x64 tile per warp), 128-node tile.
// smem:
//   phase1: A1hi[128][136] @0, A1lo @34816, W1 image @69632 (139264) -> 208896
//   phase2: A2hi[128][264] @0, A2lo @67584 (-> 135168),
//           W2 chunk double-buffer @135168 + buf*40960 (hi 20480, lo 20480)
//   epi2  : X2 fp32 [128][264] @0 (135168), aliases A2 after all mma reads
//   aux   : b1s @217088, b2s @218112, gids @219136  -> 219648 total
// ---------------------------------------------------------------------------
#define SA1_HI 0
#define SA1_LO 34816
#define SW1_HI 69632
#define SW1_LO 139264
#define SA2_HI 0
#define SA2_LO 67584
#define SB_BASE 135168
#define SB_STRIDE 40960
#define SB_LO  20480
#define SX2    0
#define SO_B1S 217088
#define SO_B2S 218112
#define SO_GID 219136
#define NODE_SMEM_BYTES 219648

extern "C" __global__ void __launch_bounds__(256, 1)
node_kernel(const float* __restrict__ h, const int* __restrict__ graph_ids,
            const float* __restrict__ b1, const float* __restrict__ b2, int n_atoms)
{
    extern __shared__ unsigned char sm[];
    const uint32_t smb = smem_to_u32(sm);
    const int tid = threadIdx.x;
    const int w   = tid >> 5;
    const int l   = tid & 31;
    const int q   = l >> 2;
    const int m   = l & 3;
    const int wm  = w >> 2;            // 0..1  (M group, 64 rows)
    const int wn  = w & 3;             // 0..3  (N group, 64 cols)
    const int Rb  = wm * 64;
    const int Cb  = wn * 64;
    const int row0 = blockIdx.x * TILE_M;

    float* b1s = (float*)(sm + SO_B1S);
    float* b2s = (float*)(sm + SO_B2S);
    int*   gids = (int*)(sm + SO_GID);

    // ---- prefetch W1 image via cp.async (overlaps A conversion below) ----
    {
        const char* w1p = (const char*)&d_W1t[0][0];
        #pragma unroll
        for (int it = 0; it < 34; it++) {
            int o = (tid + it * 256) * 16;
            cp16(smb + SW1_HI + o, w1p + o);
        }
        CP_COMMIT();
    }

    b1s[tid] = b1[tid];
    b2s[tid] = b2[tid];
    if (tid < TILE_M) {
        int r = row0 + tid;
        gids[tid] = (r < n_atoms) ? graph_ids[r] : -1;
    }

    // ---- A1: load h tile, split to bf16 hi/lo, [r][k] stride 136 halfs ----
    #pragma unroll 4
    for (int it = 0; it < 16; it++) {
        int idx = tid + it * 256;
        int r = idx >> 5, c = (idx & 31) * 4;
        float4 v = make_float4(0.f, 0.f, 0.f, 0.f);
        if (row0 + r < n_atoms)
            v = *(const float4*)(h + (size_t)(row0 + r) * DIN + c);
        uint32_t lo0, lo1;
        uint32_t hi0 = pack_hi(v.x, v.y, lo0);
        uint32_t hi1 = pack_hi(v.z, v.w, lo1);
        uint32_t off = (uint32_t)(r * 136 + c) * 2;
        *(uint2*)(sm + SA1_HI + off) = make_uint2(hi0, hi1);
        *(uint2*)(sm + SA1_LO + off) = make_uint2(lo0, lo1);
    }
    CP_WAIT0();
    __syncthreads();

    float acc[128];
    #pragma unroll
    for (int i = 0; i < 128; i++) acc[i] = 0.f;

    // ================= Layer 1: K=128, 8 k-steps =================
    #pragma unroll
    for (int ks = 0; ks < 8; ks++) {
        uint32_t aH[16], aL[16];
        #pragma unroll
        for (int mf = 0; mf < 4; mf++) {
            uint32_t ao = smb + (uint32_t)(((Rb + mf * 16 + q) * 136 + ks * 16 + m * 2) * 2);
            aH[mf*4+0] = lds32(ao + SA1_HI);        aH[mf*4+1] = lds32(ao + SA1_HI + 2176);
            aH[mf*4+2] = lds32(ao + SA1_HI + 16);   aH[mf*4+3] = lds32(ao + SA1_HI + 2192);
            aL[mf*4+0] = lds32(ao + SA1_LO);        aL[mf*4+1] = lds32(ao + SA1_LO + 2176);
            aL[mf*4+2] = lds32(ao + SA1_LO + 16);   aL[mf*4+3] = lds32(ao + SA1_LO + 2192);
        }
        #pragma unroll
        for (int nf = 0; nf < 8; nf++) {
            uint32_t bo = smb + (uint32_t)(((Cb + nf * 8 + q) * 136 + ks * 16 + m * 2) * 2);
            uint32_t bH0 = lds32(bo + SW1_HI), bH1 = lds32(bo + SW1_HI + 16);
            uint32_t bL0 = lds32(bo + SW1_LO), bL1 = lds32(bo + SW1_LO + 16);
            #pragma unroll
            for (int mf = 0; mf < 4; mf++) {
                float* d = acc + (mf * 8 + nf) * 4;
                mma_bf16(d, aH[mf*4], aH[mf*4+1], aH[mf*4+2], aH[mf*4+3], bH0, bH1);
                mma_bf16(d, aL[mf*4], aL[mf*4+1], aL[mf*4+2], aL[mf*4+3], bH0, bH1);
                mma_bf16(d, aH[mf*4], aH[mf*4+1], aH[mf*4+2], aH[mf*4+3], bL0, bL1);
            }
        }
    }
    __syncthreads();   // all layer-1 reads of A1/W1 done (W2 buffers alias W1 region)

    // ---- prefetch W2 chunks 0,1 (dest region was W1 - safe after sync) ----
    #pragma unroll
    for (int cc = 0; cc < 2; cc++) {
        const char* hp = (const char*)&d_W2t[0][cc][0];
        const char* lp = (const char*)&d_W2t[1][cc][0];
        uint32_t dst = smb + SB_BASE + cc * SB_STRIDE;
        #pragma unroll
        for (int it = 0; it < 5; it++) {
            int o = (tid + it * 256) * 16;
            cp16(dst + o, hp + o);
            cp16(dst + SB_LO + o, lp + o);
        }
        CP_COMMIT();
    }

    // ===== Epilogue 1: bias+relu, re-split -> A2 [r][c] stride 264 =====
    #pragma unroll
    for (int mf = 0; mf < 4; mf++) {
        #pragma unroll
        for (int nf = 0; nf < 8; nf++) {
            int idx = (mf * 8 + nf) * 4;
            int c = Cb + nf * 8 + m * 2;
            int R = Rb + mf * 16 + q;
            float v0 = fmaxf(acc[idx+0] + b1s[c],     0.f);
            float v1 = fmaxf(acc[idx+1] + b1s[c + 1], 0.f);
            float v2 = fmaxf(acc[idx+2] + b1s[c],     0.f);
            float v3 = fmaxf(acc[idx+3] + b1s[c + 1], 0.f);
            uint32_t lo01, lo23;
            uint32_t hi01 = pack_hi(v0, v1, lo01);
            uint32_t hi23 = pack_hi(v2, v3, lo23);
            uint32_t off = (uint32_t)((R * 264 + c) * 2);
            sts32(smb + SA2_HI + off, hi01);
            sts32(smb + SA2_HI + off + 4224, hi23);
            sts32(smb + SA2_LO + off, lo01);
            sts32(smb + SA2_LO + off + 4224, lo23);
            acc[idx+0] = 0.f; acc[idx+1] = 0.f; acc[idx+2] = 0.f; acc[idx+3] = 0.f;
        }
    }
    __syncthreads();   // A2 visible

    // ================= Layer 2: K=256 in 8 chunks of 32, double-buffered ====
    for (int c = 0; c < 8; c++) {
        if (c < 7) CP_WAIT1(); else CP_WAIT0();
        __syncthreads();
        uint32_t SB = smb + SB_BASE + (c & 1) * SB_STRIDE;
        #pragma unroll
        for (int ks = 0; ks < 2; ks++) {
            uint32_t aH[16], aL[16];
            #pragma unroll
            for (int mf = 0; mf < 4; mf++) {
                uint32_t ao = smb + (uint32_t)(((Rb + mf * 16 + q) * 264 + c * 32 + ks * 16 + m * 2) * 2);
                aH[mf*4+0] = lds32(ao + SA2_HI);        aH[mf*4+1] = lds32(ao + SA2_HI + 4224);
                aH[mf*4+2] = lds32(ao + SA2_HI + 16);   aH[mf*4+3] = lds32(ao + SA2_HI + 4240);
                aL[mf*4+0] = lds32(ao + SA2_LO);        aL[mf*4+1] = lds32(ao + SA2_LO + 4224);
                aL[mf*4+2] = lds32(ao + SA2_LO + 16);   aL[mf*4+3] = lds32(ao + SA2_LO + 4240);
            }
            #pragma unroll
            for (int nf = 0; nf < 8; nf++) {
                uint32_t bo = SB + (uint32_t)(((Cb + nf * 8 + q) * 40 + ks * 16 + m * 2) * 2);
                uint32_t bH0 = lds32(bo), bH1 = lds32(bo + 16);
                uint32_t bL0 = lds32(bo + SB_LO), bL1 = lds32(bo + SB_LO + 16);
                #pragma unroll
                for (int mf = 0; mf < 4; mf++) {
                    float* d = acc + (mf * 8 + nf) * 4;
                    mma_bf16(d, aH[mf*4], aH[mf*4+1], aH[mf*4+2], aH[mf*4+3], bH0, bH1);
                    mma_bf16(d, aL[mf*4], aL[mf*4+1], aL[mf*4+2], aL[mf*4+3], bH0, bH1);
                    mma_bf16(d, aH[mf*4], aH[mf*4+1], aH[mf*4+2], aH[mf*4+3], bL0, bL1);
                }
            }
        }
        __syncthreads();          // buffer consumed before re-fill
        if (c + 2 < 8) {
            const char* hp = (const char*)&d_W2t[0][c + 2][0];
            const char* lp = (const char*)&d_W2t[1][c + 2][0];
            uint32_t dst = smb + SB_BASE + (c & 1) * SB_STRIDE;
            #pragma unroll
            for (int it = 0; it < 5; it++) {
                int o = (tid + it * 256) * 16;
                cp16(dst + o, hp + o);
                cp16(dst + SB_LO + o, lp + o);
            }
            CP_COMMIT();
        }
    }

    // ===== Epilogue 2: bias+relu -> X2 fp32 [r][264] (aliases A2; mma done) =====
    {
        float* X2 = (float*)(sm + SX2);
        #pragma unroll
        for (int mf = 0; mf < 4; mf++) {
            #pragma unroll
            for (int nf = 0; nf < 8; nf++) {
                int idx = (mf * 8 + nf) * 4;
                int c = Cb + nf * 8 + m * 2;
                int R = Rb + mf * 16 + q;
                X2[R * 264 + c]           = fmaxf(acc[idx+0] + b2s[c],     0.f);
                X2[R * 264 + c + 1]       = fmaxf(acc[idx+1] + b2s[c + 1], 0.f);
                X2[(R + 8) * 264 + c]     = fmaxf(acc[idx+2] + b2s[c],     0.f);
                X2[(R + 8) * 264 + c + 1] = fmaxf(acc[idx+3] + b2s[c + 1], 0.f);
            }
        }
    }
    __syncthreads();

    // ===== Block-local segmented sum over sorted gids, then atomics =====
    {
        const int col = tid;
        const float* X2 = (const float*)(sm + SX2);
        int cur = -1;
        float s = 0.f;
        #pragma unroll 8
        for (int r = 0; r < TILE_M; r++) {
            int g = gids[r];
            if (g != cur) {
                if (cur >= 0) atomicAdd(&d_pooled[(size_t)cur * DH + col], s);
                cur = g;
                s = 0.f;
            }
            if (g >= 0) s += X2[r * 264 + col];
        }
        if (cur >= 0) atomicAdd(&d_pooled[(size_t)cur * DH + col], s);
    }
}

// ---------------------------------------------------------------------------
// Kernel 2: graph MLP via mma.sync split-bf16: y=relu(pooled@Wg1+bg1); out=y@Wg2+bg2
// 256 threads, 128-graph tile, same warp tiling & chunked-K pipeline as layer 2.
// smem: Ahi[128][264] @0, Alo @67584, Wg1 buffers @135168 (2 x 40960),
//       bg1s @217088, wsv @218112, rowsum[128][4] @219136 -> 221184
// ---------------------------------------------------------------------------
#define GSO_BG1 217088
#define GSO_WS  218112
#define GSO_RS  219136
#define GRAPH_SMEM_BYTES 221184

extern "C" __global__ void __launch_bounds__(256, 1)
graph_kernel(const float* __restrict__ bg1, const float* __restrict__ Wg2,
             const float* __restrict__ bg2, float* __restrict__ out, int num_graphs)
{
    extern __shared__ unsigned char sm[];
    const uint32_t smb = smem_to_u32(sm);
    const int tid = threadIdx.x;
    const int l   = tid & 31;
    const int q   = l >> 2;
    const int m   = l & 3;
    const int w   = tid >> 5;
    const int wm  = w >> 2;
    const int wn  = w & 3;
    const int Rb  = wm * 64;
    const int Cb  = wn * 64;
    const int g0  = blockIdx.x * 128;

    float* bg1s = (float*)(sm + GSO_BG1);
    float* wsv  = (float*)(sm + GSO_WS);
    float* rs   = (float*)(sm + GSO_RS);

    // prefetch Wg1 chunks 0,1 immediately (no aliasing with A region)
    #pragma unroll
    for (int cc = 0; cc < 2; cc++) {
        const char* hp = (const char*)&d_Wg1t[0][cc][0];
        const char* lp = (const char*)&d_Wg1t[1][cc][0];
        uint32_t dst = smb + SB_BASE + cc * SB_STRIDE;
        #pragma unroll
        for (int it = 0; it < 5; it++) {
            int o = (tid + it * 256) * 16;
            cp16(dst + o, hp + o);
            cp16(dst + SB_LO + o, lp + o);
        }
        CP_COMMIT();
    }

    bg1s[tid] = bg1[tid];
    wsv[tid]  = Wg2[tid];

    // ---- A: load pooled tile, split hi/lo, [r][c] stride 264 halfs ----
    #pragma unroll 4
    for (int it = 0; it < 32; it++) {
        int idx = tid + it * 256;
        int r = idx >> 6, c = (idx & 63) * 4;
        float4 v = make_float4(0.f, 0.f, 0.f, 0.f);
        if (g0 + r < num_graphs)
            v = *(const float4*)(d_pooled + (size_t)(g0 + r) * DH + c);
        uint32_t lo0, lo1;
        uint32_t hi0 = pack_hi(v.x, v.y, lo0);
        uint32_t hi1 = pack_hi(v.z, v.w, lo1);
        uint32_t off = (uint32_t)(r * 264 + c) * 2;
        *(uint2*)(sm + SA2_HI + off) = make_uint2(hi0, hi1);
        *(uint2*)(sm + SA2_LO + off) = make_uint2(lo0, lo1);
    }

    float acc[128];
    #pragma unroll
    for (int i = 0; i < 128; i++) acc[i] = 0.f;

    // ======== GEMM: K=256 in 8 chunks of 32, double-buffered ========
    for (int c = 0; c < 8; c++) {
        if (c < 7) CP_WAIT1(); else CP_WAIT0();
        __syncthreads();
        uint32_t SB = smb + SB_BASE + (c & 1) * SB_STRIDE;
        #pragma unroll
        for (int ks = 0; ks < 2; ks++) {
            uint32_t aH[16], aL[16];
            #pragma unroll
            for (int mf = 0; mf < 4; mf++) {
                uint32_t ao = smb + (uint32_t)(((Rb + mf * 16 + q) * 264 + c * 32 + ks * 16 + m * 2) * 2);
                aH[mf*4+0] = lds32(ao + SA2_HI);        aH[mf*4+1] = lds32(ao + SA2_HI + 4224);
                aH[mf*4+2] = lds32(ao + SA2_HI + 16);   aH[mf*4+3] = lds32(ao + SA2_HI + 4240);
                aL[mf*4+0] = lds32(ao + SA2_LO);        aL[mf*4+1] = lds32(ao + SA2_LO + 4224);
                aL[mf*4+2] = lds32(ao + SA2_LO + 16);   aL[mf*4+3] = lds32(ao + SA2_LO + 4240);
            }
            #pragma unroll
            for (int nf = 0; nf < 8; nf++) {
                uint32_t bo = SB + (uint32_t)(((Cb + nf * 8 + q) * 40 + ks * 16 + m * 2) * 2);
                uint32_t bH0 = lds32(bo), bH1 = lds32(bo + 16);
                uint32_t bL0 = lds32(bo + SB_LO), bL1 = lds32(bo + SB_LO + 16);
                #pragma unroll
                for (int mf = 0; mf < 4; mf++) {
                    float* d = acc + (mf * 8 + nf) * 4;
                    mma_bf16(d, aH[mf*4], aH[mf*4+1], aH[mf*4+2], aH[mf*4+3], bH0, bH1);
                    mma_bf16(d, aL[mf*4], aL[mf*4+1], aL[mf*4+2], aL[mf*4+3], bH0, bH1);
                    mma_bf16(d, aH[mf*4], aH[mf*4+1], aH[mf*4+2], aH[mf*4+3], bL0, bL1);
                }
            }
        }
        __syncthreads();
        if (c + 2 < 8) {
            const char* hp = (const char*)&d_Wg1t[0][c + 2][0];
            const char* lp = (const char*)&d_Wg1t[1][c + 2][0];
            uint32_t dst = smb + SB_BASE + (c & 1) * SB_STRIDE;
            #pragma unroll
            for (int it = 0; it < 5; it++) {
                int o = (tid + it * 256) * 16;
                cp16(dst + o, hp + o);
                cp16(dst + SB_LO + o, lp + o);
            }
            CP_COMMIT();
        }
    }

    // ===== Epilogue: relu + dot with Wg2, warp-level reduce, rowsum smem =====
    #pragma unroll
    for (int mf = 0; mf < 4; mf++) {
        float p0 = 0.f, p1 = 0.f;
        #pragma unroll
        for (int nf = 0; nf < 8; nf++) {
            int idx = (mf * 8 + nf) * 4;
            int c = Cb + nf * 8 + m * 2;
            float w0 = wsv[c], w1 = wsv[c + 1];
            p0 += fmaxf(acc[idx+0] + bg1s[c],     0.f) * w0
                + fmaxf(acc[idx+1] + bg1s[c + 1], 0.f) * w1;
            p1 += fmaxf(acc[idx+2] + bg1s[c],     0.f) * w0
                + fmaxf(acc[idx+3] + bg1s[c + 1], 0.f) * w1;
        }
        p0 += __shfl_xor_sync(0xffffffffu, p0, 1);
        p0 += __shfl_xor_sync(0xffffffffu, p0, 2);
        p1 += __shfl_xor_sync(0xffffffffu, p1, 1);
        p1 += __shfl_xor_sync(0xffffffffu, p1, 2);
        if (m == 0) {
            int R = Rb + mf * 16 + q;
            rs[R * 4 + wn]       = p0;
            rs[(R + 8) * 4 + wn] = p1;
        }
    }
    __syncthreads();
    if (tid < 128) {
        int g = g0 + tid;
        if (g < num_graphs)
            out[g] = rs[tid * 4] + rs[tid * 4 + 1] + rs[tid * 4 + 2] + rs[tid * 4 + 3] + bg2[0];
    }
}

// ---------------------------------------------------------------------------
extern "C" void kernel_launch(void* const* d_in, const int* in_sizes, int n_in,
                              void* d_out, int out_size) {
    const float* h         = (const float*)d_in[0];
    const int*   graph_ids = (const int*)  d_in[1];
    const int base = (n_in >= 11) ? 3 : 2;   // skip num_graphs scalar slot if present
    const float* W1  = (const float*)d_in[base + 0];
    const float* b1  = (const float*)d_in[base + 1];
    const float* W2  = (const float*)d_in[base + 2];
    const float* b2  = (const float*)d_in[base + 3];
    const float* Wg1 = (const float*)d_in[base + 4];
    const float* bg1 = (const float*)d_in[base + 5];
    const float* Wg2 = (const float*)d_in[base + 6];
    const float* bg2 = (const float*)d_in[base + 7];
    float* out = (float*)d_out;

    const int n_atoms = in_sizes[0] / DIN;
    const int G       = out_size;            // D_OUT = 1

    static bool attrs_set = false;
    if (!attrs_set) {
        cudaFuncSetAttribute(node_kernel,
                             cudaFuncAttributeMaxDynamicSharedMemorySize, NODE_SMEM_BYTES);
        cudaFuncSetAttribute(graph_kernel,
                             cudaFuncAttributeMaxDynamicSharedMemorySize, GRAPH_SMEM_BYTES);
        attrs_set = true;
    }

    prep_kernel<<<(DIN * DH + 2 * DH * DH + 255) / 256, 256>>>(W1, W2, Wg1);
    zero_pooled_kernel<<<512, 256>>>(G * DH);

    int nblocks = (n_atoms + TILE_M - 1) / TILE_M;
    node_kernel<<<nblocks, 256, NODE_SMEM_BYTES>>>(h, graph_ids, b1, b2, n_atoms);

    int gblocks = (G + 127) / 128;
    graph_kernel<<<gblocks, 256, GRAPH_SMEM_BYTES>>>(bg1, Wg2, bg2, out, G);
}

// round 10
// speedup vs baseline: 6.2691x; 1.0563x over previous
#include <cuda_runtime.h>
#include <cuda_bf16.h>
#include <cstdint>

#define DIN 128
#define DH  256
#define G_MAX 20000
#define TILE_M 128

// ---------------------------------------------------------------------------
// Persistent scratch
// ---------------------------------------------------------------------------
__device__ float d_pooled[G_MAX * DH];
// W1^T hi/lo, smem-image [n=256][k pad 136] bf16 (hi block then lo block)
__device__ __align__(16) __nv_bfloat16 d_W1t[2][256 * 136];
// W2^T hi/lo in 8 K-chunks of 32: [part][chunk][n=256][kk pad 40]
__device__ __align__(16) __nv_bfloat16 d_W2t[2][8][256 * 40];
// Wg1^T hi/lo, same chunking
__device__ __align__(16) __nv_bfloat16 d_Wg1t[2][8][256 * 40];

// ---------------------------------------------------------------------------
// helpers
// ---------------------------------------------------------------------------
__device__ __forceinline__ uint32_t smem_to_u32(const void* p) {
    uint32_t a;
    asm("{ .reg .u64 t; cvta.to.shared.u64 t, %1; cvt.u32.u64 %0, t; }" : "=r"(a) : "l"(p));
    return a;
}
__device__ __forceinline__ uint32_t lds32(uint32_t a) {
    uint32_t v;
    asm volatile("ld.shared.b32 %0, [%1];" : "=r"(v) : "r"(a));
    return v;
}
__device__ __forceinline__ void sts32(uint32_t a, uint32_t v) {
    asm volatile("st.shared.b32 [%0], %1;" :: "r"(a), "r"(v));
}
__device__ __forceinline__ void cp16(uint32_t s, const void* g) {
    asm volatile("cp.async.ca.shared.global [%0], [%1], 16;" :: "r"(s), "l"(g));
}
#define CP_COMMIT() asm volatile("cp.async.commit_group;" ::: "memory")
#define CP_WAIT0()  asm volatile("cp.async.wait_group 0;" ::: "memory")
#define CP_WAIT1()  asm volatile("cp.async.wait_group 1;" ::: "memory")

// m16n8k16 row.col f32.bf16.bf16.f32
__device__ __forceinline__ void mma_bf16(float* d, uint32_t a0, uint32_t a1, uint32_t a2,
                                         uint32_t a3, uint32_t b0, uint32_t b1) {
    asm volatile(
        "mma.sync.aligned.m16n8k16.row.col.f32.bf16.bf16.f32 "
        "{%0,%1,%2,%3}, {%4,%5,%6,%7}, {%8,%9}, {%0,%1,%2,%3};"
        : "+f"(d[0]), "+f"(d[1]), "+f"(d[2]), "+f"(d[3])
        : "r"(a0), "r"(a1), "r"(a2), "r"(a3), "r"(b0), "r"(b1));
}
__device__ __forceinline__ uint32_t pack_hi(float v0, float v1, uint32_t& lo_out) {
    __nv_bfloat16 h0 = __float2bfloat16(v0), h1 = __float2bfloat16(v1);
    __nv_bfloat16 l0 = __float2bfloat16(v0 - __bfloat162float(h0));
    __nv_bfloat16 l1 = __float2bfloat16(v1 - __bfloat162float(h1));
    lo_out = (uint32_t)__bfloat16_as_ushort(l0) | ((uint32_t)__bfloat16_as_ushort(l1) << 16);
    return (uint32_t)__bfloat16_as_ushort(h0) | ((uint32_t)__bfloat16_as_ushort(h1) << 16);
}

// ---------------------------------------------------------------------------
// Kernel 0: zero pooled accumulator
// ---------------------------------------------------------------------------
__global__ void zero_pooled_kernel(int total) {
    int i = blockIdx.x * blockDim.x + threadIdx.x;
    int stride = gridDim.x * blockDim.x;
    for (; i < total; i += stride) d_pooled[i] = 0.0f;
}

// ---------------------------------------------------------------------------
// Kernel P: bake W1^T / W2^T / Wg1^T into bf16 hi/lo images
// ---------------------------------------------------------------------------
__global__ void prep_kernel(const float* __restrict__ W1, const float* __restrict__ W2,
                            const float* __restrict__ Wg1) {
    int idx = blockIdx.x * blockDim.x + threadIdx.x;
    if (idx < DIN * DH) {                          // W1 [k=128][n=256]
        int k = idx / DH, n = idx % DH;
        float v = W1[idx];
        __nv_bfloat16 hi = __float2bfloat16(v);
        __nv_bfloat16 lo = __float2bfloat16(v - __bfloat162float(hi));
        d_W1t[0][n * 136 + k] = hi;
        d_W1t[1][n * 136 + k] = lo;
    } else if (idx < DIN * DH + DH * DH) {         // W2 [k=256][n=256]
        int i2 = idx - DIN * DH;
        int k = i2 / DH, n = i2 % DH;
        float v = W2[i2];
        __nv_bfloat16 hi = __float2bfloat16(v);
        __nv_bfloat16 lo = __float2bfloat16(v - __bfloat162float(hi));
        d_W2t[0][k >> 5][n * 40 + (k & 31)] = hi;
        d_W2t[1][k >> 5][n * 40 + (k & 31)] = lo;
    } else if (idx < DIN * DH + 2 * DH * DH) {     // Wg1 [k=256][n=256]
        int i2 = idx - DIN * DH - DH * DH;
        int k = i2 / DH, n = i2 % DH;
        float v = Wg1[i2];
        __nv_bfloat16 hi = __float2bfloat16(v);
        __nv_bfloat16 lo = __float2bfloat16(v - __bfloat162float(hi));
        d_Wg1t[0][k >> 5][n * 40 + (k & 31)] = hi;
        d_Wg1t[1][k >> 5][n * 40 + (k & 31)] = lo;
    }
}

// ---------------------------------------------------------------------------
// Kernel 1: fused node MLP via mma.sync split-bf16 + segmented pool
// 512 threads (16 warps, grid 4M x 4N, 32x64 tile per warp), 128-node tile.
// smem layout identical to R9 (219648 B); occupancy raised via threads.
// ---------------------------------------------------------------------------
#define SA1_HI 0
#define SA1_LO 34816
#define SW1_HI 69632
#define SW1_LO 139264
#define SA2_HI 0
#define SA2_LO 67584
#define SB_BASE 135168
#define SB_STRIDE 40960
#define SB_LO  20480
#define SX2    0
#define SO_B1S 217088
#define SO_B2S 218112
#define SO_GID 219136
#define NODE_SMEM_BYTES 219648

extern "C" __global__ void __launch_bounds__(512, 1)
node_kernel(const float* __restrict__ h, const int* __restrict__ graph_ids,
            const float* __restrict__ b1, const float* __restrict__ b2, int n_atoms)
{
    extern __shared__ unsigned char sm[];
    const uint32_t smb = smem_to_u32(sm);
    const int tid = threadIdx.x;
    const int w   = tid >> 5;
    const int l   = tid & 31;
    const int q   = l >> 2;
    const int m   = l & 3;
    const int wm  = w >> 2;            // 0..3  (M group, 32 rows)
    const int wn  = w & 3;             // 0..3  (N group, 64 cols)
    const int Rb  = wm * 32;
    const int Cb  = wn * 64;
    const int row0 = blockIdx.x * TILE_M;

    float* b1s = (float*)(sm + SO_B1S);
    float* b2s = (float*)(sm + SO_B2S);
    int*   gids = (int*)(sm + SO_GID);

    // ---- prefetch W1 image via cp.async (overlaps A conversion below) ----
    {
        const char* w1p = (const char*)&d_W1t[0][0];
        #pragma unroll
        for (int it = 0; it < 17; it++) {
            int o = (tid + it * 512) * 16;
            cp16(smb + SW1_HI + o, w1p + o);
        }
        CP_COMMIT();
    }

    if (tid < 256) {
        b1s[tid] = b1[tid];
        b2s[tid] = b2[tid];
    }
    if (tid < TILE_M) {
        int r = row0 + tid;
        gids[tid] = (r < n_atoms) ? graph_ids[r] : -1;
    }

    // ---- A1: load h tile, split to bf16 hi/lo, [r][k] stride 136 halfs ----
    #pragma unroll 4
    for (int it = 0; it < 8; it++) {
        int idx = tid + it * 512;
        int r = idx >> 5, c = (idx & 31) * 4;
        float4 v = make_float4(0.f, 0.f, 0.f, 0.f);
        if (row0 + r < n_atoms)
            v = *(const float4*)(h + (size_t)(row0 + r) * DIN + c);
        uint32_t lo0, lo1;
        uint32_t hi0 = pack_hi(v.x, v.y, lo0);
        uint32_t hi1 = pack_hi(v.z, v.w, lo1);
        uint32_t off = (uint32_t)(r * 136 + c) * 2;
        *(uint2*)(sm + SA1_HI + off) = make_uint2(hi0, hi1);
        *(uint2*)(sm + SA1_LO + off) = make_uint2(lo0, lo1);
    }
    CP_WAIT0();
    __syncthreads();

    float acc[64];
    #pragma unroll
    for (int i = 0; i < 64; i++) acc[i] = 0.f;

    // ================= Layer 1: K=128, 8 k-steps =================
    #pragma unroll
    for (int ks = 0; ks < 8; ks++) {
        uint32_t aH[8], aL[8];
        #pragma unroll
        for (int mf = 0; mf < 2; mf++) {
            uint32_t ao = smb + (uint32_t)(((Rb + mf * 16 + q) * 136 + ks * 16 + m * 2) * 2);
            aH[mf*4+0] = lds32(ao + SA1_HI);        aH[mf*4+1] = lds32(ao + SA1_HI + 2176);
            aH[mf*4+2] = lds32(ao + SA1_HI + 16);   aH[mf*4+3] = lds32(ao + SA1_HI + 2192);
            aL[mf*4+0] = lds32(ao + SA1_LO);        aL[mf*4+1] = lds32(ao + SA1_LO + 2176);
            aL[mf*4+2] = lds32(ao + SA1_LO + 16);   aL[mf*4+3] = lds32(ao + SA1_LO + 2192);
        }
        #pragma unroll
        for (int nf = 0; nf < 8; nf++) {
            uint32_t bo = smb + (uint32_t)(((Cb + nf * 8 + q) * 136 + ks * 16 + m * 2) * 2);
            uint32_t bH0 = lds32(bo + SW1_HI), bH1 = lds32(bo + SW1_HI + 16);
            uint32_t bL0 = lds32(bo + SW1_LO), bL1 = lds32(bo + SW1_LO + 16);
            #pragma unroll
            for (int mf = 0; mf < 2; mf++) {
                float* d = acc + (mf * 8 + nf) * 4;
                mma_bf16(d, aH[mf*4], aH[mf*4+1], aH[mf*4+2], aH[mf*4+3], bH0, bH1);
                mma_bf16(d, aL[mf*4], aL[mf*4+1], aL[mf*4+2], aL[mf*4+3], bH0, bH1);
                mma_bf16(d, aH[mf*4], aH[mf*4+1], aH[mf*4+2], aH[mf*4+3], bL0, bL1);
            }
        }
    }
    __syncthreads();   // all layer-1 reads of A1/W1 done (W2 buffers alias W1 region)

    // ---- prefetch W2 chunks 0,1 (dest region was W1 - safe after sync) ----
    #pragma unroll
    for (int cc = 0; cc < 2; cc++) {
        const char* hp = (const char*)&d_W2t[0][cc][0];
        const char* lp = (const char*)&d_W2t[1][cc][0];
        uint32_t dst = smb + SB_BASE + cc * SB_STRIDE;
        for (int i = tid; i < 1280; i += 512) {
            cp16(dst + i * 16, hp + i * 16);
            cp16(dst + SB_LO + i * 16, lp + i * 16);
        }
        CP_COMMIT();
    }

    // ===== Epilogue 1: bias+relu, re-split -> A2 [r][c] stride 264 =====
    #pragma unroll
    for (int mf = 0; mf < 2; mf++) {
        #pragma unroll
        for (int nf = 0; nf < 8; nf++) {
            int idx = (mf * 8 + nf) * 4;
            int c = Cb + nf * 8 + m * 2;
            int R = Rb + mf * 16 + q;
            float v0 = fmaxf(acc[idx+0] + b1s[c],     0.f);
            float v1 = fmaxf(acc[idx+1] + b1s[c + 1], 0.f);
            float v2 = fmaxf(acc[idx+2] + b1s[c],     0.f);
            float v3 = fmaxf(acc[idx+3] + b1s[c + 1], 0.f);
            uint32_t lo01, lo23;
            uint32_t hi01 = pack_hi(v0, v1, lo01);
            uint32_t hi23 = pack_hi(v2, v3, lo23);
            uint32_t off = (uint32_t)((R * 264 + c) * 2);
            sts32(smb + SA2_HI + off, hi01);
            sts32(smb + SA2_HI + off + 4224, hi23);
            sts32(smb + SA2_LO + off, lo01);
            sts32(smb + SA2_LO + off + 4224, lo23);
            acc[idx+0] = 0.f; acc[idx+1] = 0.f; acc[idx+2] = 0.f; acc[idx+3] = 0.f;
        }
    }
    __syncthreads();   // A2 visible

    // ================= Layer 2: K=256 in 8 chunks of 32, double-buffered ====
    for (int c = 0; c < 8; c++) {
        if (c < 7) CP_WAIT1(); else CP_WAIT0();
        __syncthreads();
        uint32_t SB = smb + SB_BASE + (c & 1) * SB_STRIDE;
        #pragma unroll
        for (int ks = 0; ks < 2; ks++) {
            uint32_t aH[8], aL[8];
            #pragma unroll
            for (int mf = 0; mf < 2; mf++) {
                uint32_t ao = smb + (uint32_t)(((Rb + mf * 16 + q) * 264 + c * 32 + ks * 16 + m * 2) * 2);
                aH[mf*4+0] = lds32(ao + SA2_HI);        aH[mf*4+1] = lds32(ao + SA2_HI + 4224);
                aH[mf*4+2] = lds32(ao + SA2_HI + 16);   aH[mf*4+3] = lds32(ao + SA2_HI + 4240);
                aL[mf*4+0] = lds32(ao + SA2_LO);        aL[mf*4+1] = lds32(ao + SA2_LO + 4224);
                aL[mf*4+2] = lds32(ao + SA2_LO + 16);   aL[mf*4+3] = lds32(ao + SA2_LO + 4240);
            }
            #pragma unroll
            for (int nf = 0; nf < 8; nf++) {
                uint32_t bo = SB + (uint32_t)(((Cb + nf * 8 + q) * 40 + ks * 16 + m * 2) * 2);
                uint32_t bH0 = lds32(bo), bH1 = lds32(bo + 16);
                uint32_t bL0 = lds32(bo + SB_LO), bL1 = lds32(bo + SB_LO + 16);
                #pragma unroll
                for (int mf = 0; mf < 2; mf++) {
                    float* d = acc + (mf * 8 + nf) * 4;
                    mma_bf16(d, aH[mf*4], aH[mf*4+1], aH[mf*4+2], aH[mf*4+3], bH0, bH1);
                    mma_bf16(d, aL[mf*4], aL[mf*4+1], aL[mf*4+2], aL[mf*4+3], bH0, bH1);
                    mma_bf16(d, aH[mf*4], aH[mf*4+1], aH[mf*4+2], aH[mf*4+3], bL0, bL1);
                }
            }
        }
        __syncthreads();          // buffer consumed before re-fill
        if (c + 2 < 8) {
            const char* hp = (const char*)&d_W2t[0][c + 2][0];
            const char* lp = (const char*)&d_W2t[1][c + 2][0];
            uint32_t dst = smb + SB_BASE + (c & 1) * SB_STRIDE;
            for (int i = tid; i < 1280; i += 512) {
                cp16(dst + i * 16, hp + i * 16);
                cp16(dst + SB_LO + i * 16, lp + i * 16);
            }
            CP_COMMIT();
        }
    }

    // ===== Epilogue 2: bias+relu -> X2 fp32 [r][264] (aliases A2; mma done) =====
    {
        float* X2 = (float*)(sm + SX2);
        #pragma unroll
        for (int mf = 0; mf < 2; mf++) {
            #pragma unroll
            for (int nf = 0; nf < 8; nf++) {
                int idx = (mf * 8 + nf) * 4;
                int c = Cb + nf * 8 + m * 2;
                int R = Rb + mf * 16 + q;
                X2[R * 264 + c]           = fmaxf(acc[idx+0] + b2s[c],     0.f);
                X2[R * 264 + c + 1]       = fmaxf(acc[idx+1] + b2s[c + 1], 0.f);
                X2[(R + 8) * 264 + c]     = fmaxf(acc[idx+2] + b2s[c],     0.f);
                X2[(R + 8) * 264 + c + 1] = fmaxf(acc[idx+3] + b2s[c + 1], 0.f);
            }
        }
    }
    __syncthreads();

    // ===== Block-local segmented sum over sorted gids, then atomics =====
    // Lower 256 threads walk rows [0,64), upper walk [64,128). Segments spanning
    // the boundary issue two atomics — correct, atomicAdd is associative.
    {
        const int col  = tid & 255;
        const int rlo  = (tid >> 8) * 64;
        const float* X2 = (const float*)(sm + SX2);
        int cur = -1;
        float s = 0.f;
        #pragma unroll 8
        for (int rr = 0; rr < 64; rr++) {
            int r = rlo + rr;
            int g = gids[r];
            if (g != cur) {
                if (cur >= 0) atomicAdd(&d_pooled[(size_t)cur * DH + col], s);
                cur = g;
                s = 0.f;
            }
            if (g >= 0) s += X2[r * 264 + col];
        }
        if (cur >= 0) atomicAdd(&d_pooled[(size_t)cur * DH + col], s);
    }
}

// ---------------------------------------------------------------------------
// Kernel 2: graph MLP via mma.sync split-bf16 (unchanged from R9, 56us)
// ---------------------------------------------------------------------------
#define GSO_BG1 217088
#define GSO_WS  218112
#define GSO_RS  219136
#define GRAPH_SMEM_BYTES 221184

extern "C" __global__ void __launch_bounds__(256, 1)
graph_kernel(const float* __restrict__ bg1, const float* __restrict__ Wg2,
             const float* __restrict__ bg2, float* __restrict__ out, int num_graphs)
{
    extern __shared__ unsigned char sm[];
    const uint32_t smb = smem_to_u32(sm);
    const int tid = threadIdx.x;
    const int l   = tid & 31;
    const int q   = l >> 2;
    const int m   = l & 3;
    const int w   = tid >> 5;
    const int wm  = w >> 2;
    const int wn  = w & 3;
    const int Rb  = wm * 64;
    const int Cb  = wn * 64;
    const int g0  = blockIdx.x * 128;

    float* bg1s = (float*)(sm + GSO_BG1);
    float* wsv  = (float*)(sm + GSO_WS);
    float* rs   = (float*)(sm + GSO_RS);

    #pragma unroll
    for (int cc = 0; cc < 2; cc++) {
        const char* hp = (const char*)&d_Wg1t[0][cc][0];
        const char* lp = (const char*)&d_Wg1t[1][cc][0];
        uint32_t dst = smb + SB_BASE + cc * SB_STRIDE;
        #pragma unroll
        for (int it = 0; it < 5; it++) {
            int o = (tid + it * 256) * 16;
            cp16(dst + o, hp + o);
            cp16(dst + SB_LO + o, lp + o);
        }
        CP_COMMIT();
    }

    bg1s[tid] = bg1[tid];
    wsv[tid]  = Wg2[tid];

    #pragma unroll 4
    for (int it = 0; it < 32; it++) {
        int idx = tid + it * 256;
        int r = idx >> 6, c = (idx & 63) * 4;
        float4 v = make_float4(0.f, 0.f, 0.f, 0.f);
        if (g0 + r < num_graphs)
            v = *(const float4*)(d_pooled + (size_t)(g0 + r) * DH + c);
        uint32_t lo0, lo1;
        uint32_t hi0 = pack_hi(v.x, v.y, lo0);
        uint32_t hi1 = pack_hi(v.z, v.w, lo1);
        uint32_t off = (uint32_t)(r * 264 + c) * 2;
        *(uint2*)(sm + SA2_HI + off) = make_uint2(hi0, hi1);
        *(uint2*)(sm + SA2_LO + off) = make_uint2(lo0, lo1);
    }

    float acc[128];
    #pragma unroll
    for (int i = 0; i < 128; i++) acc[i] = 0.f;

    for (int c = 0; c < 8; c++) {
        if (c < 7) CP_WAIT1(); else CP_WAIT0();
        __syncthreads();
        uint32_t SB = smb + SB_BASE + (c & 1) * SB_STRIDE;
        #pragma unroll
        for (int ks = 0; ks < 2; ks++) {
            uint32_t aH[16], aL[16];
            #pragma unroll
            for (int mf = 0; mf < 4; mf++) {
                uint32_t ao = smb + (uint32_t)(((Rb + mf * 16 + q) * 264 + c * 32 + ks * 16 + m * 2) * 2);
                aH[mf*4+0] = lds32(ao + SA2_HI);        aH[mf*4+1] = lds32(ao + SA2_HI + 4224);
                aH[mf*4+2] = lds32(ao + SA2_HI + 16);   aH[mf*4+3] = lds32(ao + SA2_HI + 4240);
                aL[mf*4+0] = lds32(ao + SA2_LO);        aL[mf*4+1] = lds32(ao + SA2_LO + 4224);
                aL[mf*4+2] = lds32(ao + SA2_LO + 16);   aL[mf*4+3] = lds32(ao + SA2_LO + 4240);
            }
            #pragma unroll
            for (int nf = 0; nf < 8; nf++) {
                uint32_t bo = SB + (uint32_t)(((Cb + nf * 8 + q) * 40 + ks * 16 + m * 2) * 2);
                uint32_t bH0 = lds32(bo), bH1 = lds32(bo + 16);
                uint32_t bL0 = lds32(bo + SB_LO), bL1 = lds32(bo + SB_LO + 16);
                #pragma unroll
                for (int mf = 0; mf < 4; mf++) {
                    float* d = acc + (mf * 8 + nf) * 4;
                    mma_bf16(d, aH[mf*4], aH[mf*4+1], aH[mf*4+2], aH[mf*4+3], bH0, bH1);
                    mma_bf16(d, aL[mf*4], aL[mf*4+1], aL[mf*4+2], aL[mf*4+3], bH0, bH1);
                    mma_bf16(d, aH[mf*4], aH[mf*4+1], aH[mf*4+2], aH[mf*4+3], bL0, bL1);
                }
            }
        }
        __syncthreads();
        if (c + 2 < 8) {
            const char* hp = (const char*)&d_Wg1t[0][c + 2][0];
            const char* lp = (const char*)&d_Wg1t[1][c + 2][0];
            uint32_t dst = smb + SB_BASE + (c & 1) * SB_STRIDE;
            #pragma unroll
            for (int it = 0; it < 5; it++) {
                int o = (tid + it * 256) * 16;
                cp16(dst + o, hp + o);
                cp16(dst + SB_LO + o, lp + o);
            }
            CP_COMMIT();
        }
    }

    #pragma unroll
    for (int mf = 0; mf < 4; mf++) {
        float p0 = 0.f, p1 = 0.f;
        #pragma unroll
        for (int nf = 0; nf < 8; nf++) {
            int idx = (mf * 8 + nf) * 4;
            int c = Cb + nf * 8 + m * 2;
            float w0 = wsv[c], w1 = wsv[c + 1];
            p0 += fmaxf(acc[idx+0] + bg1s[c],     0.f) * w0
                + fmaxf(acc[idx+1] + bg1s[c + 1], 0.f) * w1;
            p1 += fmaxf(acc[idx+2] + bg1s[c],     0.f) * w0
                + fmaxf(acc[idx+3] + bg1s[c + 1], 0.f) * w1;
        }
        p0 += __shfl_xor_sync(0xffffffffu, p0, 1);
        p0 += __shfl_xor_sync(0xffffffffu, p0, 2);
        p1 += __shfl_xor_sync(0xffffffffu, p1, 1);
        p1 += __shfl_xor_sync(0xffffffffu, p1, 2);
        if (m == 0) {
            int R = Rb + mf * 16 + q;
            rs[R * 4 + wn]       = p0;
            rs[(R + 8) * 4 + wn] = p1;
        }
    }
    __syncthreads();
    if (tid < 128) {
        int g = g0 + tid;
        if (g < num_graphs)
            out[g] = rs[tid * 4] + rs[tid * 4 + 1] + rs[tid * 4 + 2] + rs[tid * 4 + 3] + bg2[0];
    }
}

// ---------------------------------------------------------------------------
extern "C" void kernel_launch(void* const* d_in, const int* in_sizes, int n_in,
                              void* d_out, int out_size) {
    const float* h         = (const float*)d_in[0];
    const int*   graph_ids = (const int*)  d_in[1];
    const int base = (n_in >= 11) ? 3 : 2;   // skip num_graphs scalar slot if present
    const float* W1  = (const float*)d_in[base + 0];
    const float* b1  = (const float*)d_in[base + 1];
    const float* W2  = (const float*)d_in[base + 2];
    const float* b2  = (const float*)d_in[base + 3];
    const float* Wg1 = (const float*)d_in[base + 4];
    const float* bg1 = (const float*)d_in[base + 5];
    const float* Wg2 = (const float*)d_in[base + 6];
    const float* bg2 = (const float*)d_in[base + 7];
    float* out = (float*)d_out;

    const int n_atoms = in_sizes[0] / DIN;
    const int G       = out_size;            // D_OUT = 1

    static bool attrs_set = false;
    if (!attrs_set) {
        cudaFuncSetAttribute(node_kernel,
                             cudaFuncAttributeMaxDynamicSharedMemorySize, NODE_SMEM_BYTES);
        cudaFuncSetAttribute(graph_kernel,
                             cudaFuncAttributeMaxDynamicSharedMemorySize, GRAPH_SMEM_BYTES);
        attrs_set = true;
    }

    prep_kernel<<<(DIN * DH + 2 * DH * DH + 255) / 256, 256>>>(W1, W2, Wg1);
    zero_pooled_kernel<<<512, 256>>>(G * DH);

    int nblocks = (n_atoms + TILE_M - 1) / TILE_M;
    node_kernel<<<nblocks, 512, NODE_SMEM_BYTES>>>(h, graph_ids, b1, b2, n_atoms);

    int gblocks = (G + 127) / 128;
    graph_kernel<<<gblocks, 256, GRAPH_SMEM_BYTES>>>(bg1, Wg2, bg2, out, G);
}

// round 11
// speedup vs baseline: 8.5033x; 1.3564x over previous
#include <cuda_runtime.h>
#include <cuda_bf16.h>
#include <cuda_fp16.h>
#include <cstdint>

#define DIN 128
#define DH  256
#define G_MAX 20000
#define TILE_M 128

// ---------------------------------------------------------------------------
// Persistent scratch
// ---------------------------------------------------------------------------
__device__ float d_pooled[G_MAX * DH];
// W1^T hi (fp16), smem-image [n=256][k pad 136]
__device__ __align__(16) __half d_W1h[256 * 136];
// W2^T hi (fp16) in 4 K-chunks of 64: [chunk][n=256][kk pad 72]
__device__ __align__(16) __half d_W2h[4][256 * 72];
// Wg1^T hi/lo (bf16, 3-term path) in 8 K-chunks of 32: [part][chunk][n=256][kk pad 40]
__device__ __align__(16) __nv_bfloat16 d_Wg1t[2][8][256 * 40];

// ---------------------------------------------------------------------------
// helpers
// ---------------------------------------------------------------------------
__device__ __forceinline__ uint32_t smem_to_u32(const void* p) {
    uint32_t a;
    asm("{ .reg .u64 t; cvta.to.shared.u64 t, %1; cvt.u32.u64 %0, t; }" : "=r"(a) : "l"(p));
    return a;
}
__device__ __forceinline__ uint32_t lds32(uint32_t a) {
    uint32_t v;
    asm volatile("ld.shared.b32 %0, [%1];" : "=r"(v) : "r"(a));
    return v;
}
__device__ __forceinline__ void sts32(uint32_t a, uint32_t v) {
    asm volatile("st.shared.b32 [%0], %1;" :: "r"(a), "r"(v));
}
__device__ __forceinline__ void cp16(uint32_t s, const void* g) {
    asm volatile("cp.async.ca.shared.global [%0], [%1], 16;" :: "r"(s), "l"(g));
}
#define CP_COMMIT() asm volatile("cp.async.commit_group;" ::: "memory")
#define CP_WAITN(n) asm volatile("cp.async.wait_group %0;" :: "n"(n) : "memory")

// m16n8k16 fp16 inputs, fp32 accum
__device__ __forceinline__ void mma_f16(float* d, uint32_t a0, uint32_t a1, uint32_t a2,
                                        uint32_t a3, uint32_t b0, uint32_t b1) {
    asm volatile(
        "mma.sync.aligned.m16n8k16.row.col.f32.f16.f16.f32 "
        "{%0,%1,%2,%3}, {%4,%5,%6,%7}, {%8,%9}, {%0,%1,%2,%3};"
        : "+f"(d[0]), "+f"(d[1]), "+f"(d[2]), "+f"(d[3])
        : "r"(a0), "r"(a1), "r"(a2), "r"(a3), "r"(b0), "r"(b1));
}
// m16n8k16 bf16 inputs, fp32 accum (graph kernel, 3-term path)
__device__ __forceinline__ void mma_bf16(float* d, uint32_t a0, uint32_t a1, uint32_t a2,
                                         uint32_t a3, uint32_t b0, uint32_t b1) {
    asm volatile(
        "mma.sync.aligned.m16n8k16.row.col.f32.bf16.bf16.f32 "
        "{%0,%1,%2,%3}, {%4,%5,%6,%7}, {%8,%9}, {%0,%1,%2,%3};"
        : "+f"(d[0]), "+f"(d[1]), "+f"(d[2]), "+f"(d[3])
        : "r"(a0), "r"(a1), "r"(a2), "r"(a3), "r"(b0), "r"(b1));
}
// fp16 two-term split pack: returns packed hi pair, outputs packed residual pair
__device__ __forceinline__ uint32_t packh_hi(float v0, float v1, uint32_t& lo_out) {
    __half h0 = __float2half(v0), h1 = __float2half(v1);
    __half l0 = __float2half(v0 - __half2float(h0));
    __half l1 = __float2half(v1 - __half2float(h1));
    lo_out = (uint32_t)__half_as_ushort(l0) | ((uint32_t)__half_as_ushort(l1) << 16);
    return (uint32_t)__half_as_ushort(h0) | ((uint32_t)__half_as_ushort(h1) << 16);
}
// bf16 split pack (graph kernel)
__device__ __forceinline__ uint32_t packb_hi(float v0, float v1, uint32_t& lo_out) {
    __nv_bfloat16 h0 = __float2bfloat16(v0), h1 = __float2bfloat16(v1);
    __nv_bfloat16 l0 = __float2bfloat16(v0 - __bfloat162float(h0));
    __nv_bfloat16 l1 = __float2bfloat16(v1 - __bfloat162float(h1));
    lo_out = (uint32_t)__bfloat16_as_ushort(l0) | ((uint32_t)__bfloat16_as_ushort(l1) << 16);
    return (uint32_t)__bfloat16_as_ushort(h0) | ((uint32_t)__bfloat16_as_ushort(h1) << 16);
}

// ---------------------------------------------------------------------------
// Kernel 0: zero pooled accumulator
// ---------------------------------------------------------------------------
__global__ void zero_pooled_kernel(int total) {
    int i = blockIdx.x * blockDim.x + threadIdx.x;
    int stride = gridDim.x * blockDim.x;
    for (; i < total; i += stride) d_pooled[i] = 0.0f;
}

// ---------------------------------------------------------------------------
// Kernel P: bake W1^T (fp16 hi), W2^T (fp16 hi), Wg1^T (bf16 hi/lo)
// ---------------------------------------------------------------------------
__global__ void prep_kernel(const float* __restrict__ W1, const float* __restrict__ W2,
                            const float* __restrict__ Wg1) {
    int idx = blockIdx.x * blockDim.x + threadIdx.x;
    if (idx < DIN * DH) {                          // W1 [k=128][n=256]
        int k = idx / DH, n = idx % DH;
        d_W1h[n * 136 + k] = __float2half(W1[idx]);
    } else if (idx < DIN * DH + DH * DH) {         // W2 [k=256][n=256]
        int i2 = idx - DIN * DH;
        int k = i2 / DH, n = i2 % DH;
        d_W2h[k >> 6][n * 72 + (k & 63)] = __float2half(W2[i2]);
    } else if (idx < DIN * DH + 2 * DH * DH) {     // Wg1 [k=256][n=256]
        int i2 = idx - DIN * DH - DH * DH;
        int k = i2 / DH, n = i2 % DH;
        float v = Wg1[i2];
        __nv_bfloat16 hi = __float2bfloat16(v);
        __nv_bfloat16 lo = __float2bfloat16(v - __bfloat162float(hi));
        d_Wg1t[0][k >> 5][n * 40 + (k & 31)] = hi;
        d_Wg1t[1][k >> 5][n * 40 + (k & 31)] = lo;
    }
}

// ---------------------------------------------------------------------------
// Kernel 1: fused node MLP via mma.sync fp16 2-term split + segmented pool
// 512 threads (16 warps, grid 4M x 4N, 32x64 per-warp tile), 128-node tile.
// smem:
//   phase1: A1hi[128][136]h @0 (34816), A1lo @34816 (->69632),
//           W1hi image @69632 (69632 -> 139264)
//   W2 double-buffer @139264 + buf*36864 (chunks of K=64, hi only) -> 212992
//   phase2: A2hi[128][264]h @0 (67584), A2lo @67584 (->135168)
//   epi2  : X2 fp32 [128][264] @0 (135168), aliases A2 after all mma reads
//   aux   : b1s @212992, b2s @214016, gids @215040 -> 215552 total
// ---------------------------------------------------------------------------
#define SA1_HI 0
#define SA1_LO 34816
#define SW1    69632
#define NB_BASE 139264
#define NB_STRIDE 36864
#define SA2_HI 0
#define SA2_LO 67584
#define SX2    0
#define SO_B1S 212992
#define SO_B2S 214016
#define SO_GID 215040
#define NODE_SMEM_BYTES 215552

extern "C" __global__ void __launch_bounds__(512, 1)
node_kernel(const float* __restrict__ h, const int* __restrict__ graph_ids,
            const float* __restrict__ b1, const float* __restrict__ b2, int n_atoms)
{
    extern __shared__ unsigned char sm[];
    const uint32_t smb = smem_to_u32(sm);
    const int tid = threadIdx.x;
    const int w   = tid >> 5;
    const int l   = tid & 31;
    const int q   = l >> 2;
    const int m   = l & 3;
    const int wm  = w >> 2;            // 0..3  (M group, 32 rows)
    const int wn  = w & 3;             // 0..3  (N group, 64 cols)
    const int Rb  = wm * 32;
    const int Cb  = wn * 64;
    const int row0 = blockIdx.x * TILE_M;

    float* b1s = (float*)(sm + SO_B1S);
    float* b2s = (float*)(sm + SO_B2S);
    int*   gids = (int*)(sm + SO_GID);

    // ---- prefetch W1 image (group 0), then W2 chunks 0,1 (groups 1,2) ----
    {
        const char* p = (const char*)&d_W1h[0];
        for (int i = tid; i < 4352; i += 512) cp16(smb + SW1 + i * 16, p + i * 16);
        CP_COMMIT();
    }
    #pragma unroll
    for (int cc = 0; cc < 2; cc++) {
        const char* p = (const char*)&d_W2h[cc][0];
        uint32_t dst = smb + NB_BASE + cc * NB_STRIDE;
        for (int i = tid; i < 2304; i += 512) cp16(dst + i * 16, p + i * 16);
        CP_COMMIT();
    }

    if (tid < 256) {
        b1s[tid] = b1[tid];
        b2s[tid] = b2[tid];
    }
    if (tid < TILE_M) {
        int r = row0 + tid;
        gids[tid] = (r < n_atoms) ? graph_ids[r] : -1;
    }

    // ---- A1: load h tile, fp16 2-term split, [r][k] stride 136 halfs ----
    #pragma unroll 4
    for (int it = 0; it < 8; it++) {
        int idx = tid + it * 512;
        int r = idx >> 5, c = (idx & 31) * 4;
        float4 v = make_float4(0.f, 0.f, 0.f, 0.f);
        if (row0 + r < n_atoms)
            v = *(const float4*)(h + (size_t)(row0 + r) * DIN + c);
        uint32_t lo0, lo1;
        uint32_t hi0 = packh_hi(v.x, v.y, lo0);
        uint32_t hi1 = packh_hi(v.z, v.w, lo1);
        uint32_t off = (uint32_t)(r * 136 + c) * 2;
        *(uint2*)(sm + SA1_HI + off) = make_uint2(hi0, hi1);
        *(uint2*)(sm + SA1_LO + off) = make_uint2(lo0, lo1);
    }
    CP_WAITN(2);          // W1 resident (W2 chunks may still be in flight)
    __syncthreads();

    float acc[64];
    #pragma unroll
    for (int i = 0; i < 64; i++) acc[i] = 0.f;

    // ================= Layer 1: K=128, 8 k-steps, 2 MMAs per tile ==========
    #pragma unroll
    for (int ks = 0; ks < 8; ks++) {
        uint32_t aH[8], aL[8];
        #pragma unroll
        for (int mf = 0; mf < 2; mf++) {
            uint32_t ao = smb + (uint32_t)(((Rb + mf * 16 + q) * 136 + ks * 16 + m * 2) * 2);
            aH[mf*4+0] = lds32(ao + SA1_HI);        aH[mf*4+1] = lds32(ao + SA1_HI + 2176);
            aH[mf*4+2] = lds32(ao + SA1_HI + 16);   aH[mf*4+3] = lds32(ao + SA1_HI + 2192);
            aL[mf*4+0] = lds32(ao + SA1_LO);        aL[mf*4+1] = lds32(ao + SA1_LO + 2176);
            aL[mf*4+2] = lds32(ao + SA1_LO + 16);   aL[mf*4+3] = lds32(ao + SA1_LO + 2192);
        }
        #pragma unroll
        for (int nf = 0; nf < 8; nf++) {
            uint32_t bo = smb + SW1 + (uint32_t)(((Cb + nf * 8 + q) * 136 + ks * 16 + m * 2) * 2);
            uint32_t bH0 = lds32(bo), bH1 = lds32(bo + 16);
            #pragma unroll
            for (int mf = 0; mf < 2; mf++) {
                float* d = acc + (mf * 8 + nf) * 4;
                mma_f16(d, aH[mf*4], aH[mf*4+1], aH[mf*4+2], aH[mf*4+3], bH0, bH1);
                mma_f16(d, aL[mf*4], aL[mf*4+1], aL[mf*4+2], aL[mf*4+3], bH0, bH1);
            }
        }
    }
    __syncthreads();   // layer-1 reads of A1/W1 done; A2 may overwrite them

    // ===== Epilogue 1: bias+relu, fp16 re-split -> A2 [r][c] stride 264 =====
    #pragma unroll
    for (int mf = 0; mf < 2; mf++) {
        #pragma unroll
        for (int nf = 0; nf < 8; nf++) {
            int idx = (mf * 8 + nf) * 4;
            int c = Cb + nf * 8 + m * 2;
            int R = Rb + mf * 16 + q;
            float v0 = fmaxf(acc[idx+0] + b1s[c],     0.f);
            float v1 = fmaxf(acc[idx+1] + b1s[c + 1], 0.f);
            float v2 = fmaxf(acc[idx+2] + b1s[c],     0.f);
            float v3 = fmaxf(acc[idx+3] + b1s[c + 1], 0.f);
            uint32_t lo01, lo23;
            uint32_t hi01 = packh_hi(v0, v1, lo01);
            uint32_t hi23 = packh_hi(v2, v3, lo23);
            uint32_t off = (uint32_t)((R * 264 + c) * 2);
            sts32(smb + SA2_HI + off, hi01);
            sts32(smb + SA2_HI + off + 4224, hi23);
            sts32(smb + SA2_LO + off, lo01);
            sts32(smb + SA2_LO + off + 4224, lo23);
            acc[idx+0] = 0.f; acc[idx+1] = 0.f; acc[idx+2] = 0.f; acc[idx+3] = 0.f;
        }
    }
    __syncthreads();   // A2 visible

    // ========== Layer 2: K=256 in 4 chunks of 64, double-buffered ==========
    for (int c = 0; c < 4; c++) {
        if (c < 3) CP_WAITN(1); else CP_WAITN(0);
        __syncthreads();
        uint32_t SB = smb + NB_BASE + (c & 1) * NB_STRIDE;
        #pragma unroll
        for (int ks = 0; ks < 4; ks++) {
            uint32_t aH[8], aL[8];
            #pragma unroll
            for (int mf = 0; mf < 2; mf++) {
                uint32_t ao = smb + (uint32_t)(((Rb + mf * 16 + q) * 264 + c * 64 + ks * 16 + m * 2) * 2);
                aH[mf*4+0] = lds32(ao + SA2_HI);        aH[mf*4+1] = lds32(ao + SA2_HI + 4224);
                aH[mf*4+2] = lds32(ao + SA2_HI + 16);   aH[mf*4+3] = lds32(ao + SA2_HI + 4240);
                aL[mf*4+0] = lds32(ao + SA2_LO);        aL[mf*4+1] = lds32(ao + SA2_LO + 4224);
                aL[mf*4+2] = lds32(ao + SA2_LO + 16);   aL[mf*4+3] = lds32(ao + SA2_LO + 4240);
            }
            #pragma unroll
            for (int nf = 0; nf < 8; nf++) {
                uint32_t bo = SB + (uint32_t)(((Cb + nf * 8 + q) * 72 + ks * 16 + m * 2) * 2);
                uint32_t bH0 = lds32(bo), bH1 = lds32(bo + 16);
                #pragma unroll
                for (int mf = 0; mf < 2; mf++) {
                    float* d = acc + (mf * 8 + nf) * 4;
                    mma_f16(d, aH[mf*4], aH[mf*4+1], aH[mf*4+2], aH[mf*4+3], bH0, bH1);
                    mma_f16(d, aL[mf*4], aL[mf*4+1], aL[mf*4+2], aL[mf*4+3], bH0, bH1);
                }
            }
        }
        __syncthreads();          // buffer consumed before re-fill
        if (c + 2 < 4) {
            const char* p = (const char*)&d_W2h[c + 2][0];
            uint32_t dst = smb + NB_BASE + (c & 1) * NB_STRIDE;
            for (int i = tid; i < 2304; i += 512) cp16(dst + i * 16, p + i * 16);
            CP_COMMIT();
        }
    }

    // ===== Epilogue 2: bias+relu -> X2 fp32 [r][264] (aliases A2; mma done) =====
    {
        float* X2 = (float*)(sm + SX2);
        #pragma unroll
        for (int mf = 0; mf < 2; mf++) {
            #pragma unroll
            for (int nf = 0; nf < 8; nf++) {
                int idx = (mf * 8 + nf) * 4;
                int c = Cb + nf * 8 + m * 2;
                int R = Rb + mf * 16 + q;
                X2[R * 264 + c]           = fmaxf(acc[idx+0] + b2s[c],     0.f);
                X2[R * 264 + c + 1]       = fmaxf(acc[idx+1] + b2s[c + 1], 0.f);
                X2[(R + 8) * 264 + c]     = fmaxf(acc[idx+2] + b2s[c],     0.f);
                X2[(R + 8) * 264 + c + 1] = fmaxf(acc[idx+3] + b2s[c + 1], 0.f);
            }
        }
    }
    __syncthreads();

    // ===== Block-local segmented sum over sorted gids, then atomics =====
    {
        const int col  = tid & 255;
        const int rlo  = (tid >> 8) * 64;
        const float* X2 = (const float*)(sm + SX2);
        int cur = -1;
        float s = 0.f;
        #pragma unroll 8
        for (int rr = 0; rr < 64; rr++) {
            int r = rlo + rr;
            int g = gids[r];
            if (g != cur) {
                if (cur >= 0) atomicAdd(&d_pooled[(size_t)cur * DH + col], s);
                cur = g;
                s = 0.f;
            }
            if (g >= 0) s += X2[r * 264 + col];
        }
        if (cur >= 0) atomicAdd(&d_pooled[(size_t)cur * DH + col], s);
    }
}

// ---------------------------------------------------------------------------
// Kernel 2: graph MLP via mma.sync split-bf16 3-term (unchanged, 56us)
// ---------------------------------------------------------------------------
#define GB_BASE 135168
#define GB_STRIDE 40960
#define GB_LO  20480
#define GSO_BG1 217088
#define GSO_WS  218112
#define GSO_RS  219136
#define GRAPH_SMEM_BYTES 221184

extern "C" __global__ void __launch_bounds__(256, 1)
graph_kernel(const float* __restrict__ bg1, const float* __restrict__ Wg2,
             const float* __restrict__ bg2, float* __restrict__ out, int num_graphs)
{
    extern __shared__ unsigned char sm[];
    const uint32_t smb = smem_to_u32(sm);
    const int tid = threadIdx.x;
    const int l   = tid & 31;
    const int q   = l >> 2;
    const int m   = l & 3;
    const int w   = tid >> 5;
    const int wm  = w >> 2;
    const int wn  = w & 3;
    const int Rb  = wm * 64;
    const int Cb  = wn * 64;
    const int g0  = blockIdx.x * 128;

    float* bg1s = (float*)(sm + GSO_BG1);
    float* wsv  = (float*)(sm + GSO_WS);
    float* rs   = (float*)(sm + GSO_RS);

    #pragma unroll
    for (int cc = 0; cc < 2; cc++) {
        const char* hp = (const char*)&d_Wg1t[0][cc][0];
        const char* lp = (const char*)&d_Wg1t[1][cc][0];
        uint32_t dst = smb + GB_BASE + cc * GB_STRIDE;
        #pragma unroll
        for (int it = 0; it < 5; it++) {
            int o = (tid + it * 256) * 16;
            cp16(dst + o, hp + o);
            cp16(dst + GB_LO + o, lp + o);
        }
        CP_COMMIT();
    }

    bg1s[tid] = bg1[tid];
    wsv[tid]  = Wg2[tid];

    #pragma unroll 4
    for (int it = 0; it < 32; it++) {
        int idx = tid + it * 256;
        int r = idx >> 6, c = (idx & 63) * 4;
        float4 v = make_float4(0.f, 0.f, 0.f, 0.f);
        if (g0 + r < num_graphs)
            v = *(const float4*)(d_pooled + (size_t)(g0 + r) * DH + c);
        uint32_t lo0, lo1;
        uint32_t hi0 = packb_hi(v.x, v.y, lo0);
        uint32_t hi1 = packb_hi(v.z, v.w, lo1);
        uint32_t off = (uint32_t)(r * 264 + c) * 2;
        *(uint2*)(sm + SA2_HI + off) = make_uint2(hi0, hi1);
        *(uint2*)(sm + SA2_LO + off) = make_uint2(lo0, lo1);
    }

    float acc[128];
    #pragma unroll
    for (int i = 0; i < 128; i++) acc[i] = 0.f;

    for (int c = 0; c < 8; c++) {
        if (c < 7) CP_WAITN(1); else CP_WAITN(0);
        __syncthreads();
        uint32_t SB = smb + GB_BASE + (c & 1) * GB_STRIDE;
        #pragma unroll
        for (int ks = 0; ks < 2; ks++) {
            uint32_t aH[16], aL[16];
            #pragma unroll
            for (int mf = 0; mf < 4; mf++) {
                uint32_t ao = smb + (uint32_t)(((Rb + mf * 16 + q) * 264 + c * 32 + ks * 16 + m * 2) * 2);
                aH[mf*4+0] = lds32(ao + SA2_HI);        aH[mf*4+1] = lds32(ao + SA2_HI + 4224);
                aH[mf*4+2] = lds32(ao + SA2_HI + 16);   aH[mf*4+3] = lds32(ao + SA2_HI + 4240);
                aL[mf*4+0] = lds32(ao + SA2_LO);        aL[mf*4+1] = lds32(ao + SA2_LO + 4224);
                aL[mf*4+2] = lds32(ao + SA2_LO + 16);   aL[mf*4+3] = lds32(ao + SA2_LO + 4240);
            }
            #pragma unroll
            for (int nf = 0; nf < 8; nf++) {
                uint32_t bo = SB + (uint32_t)(((Cb + nf * 8 + q) * 40 + ks * 16 + m * 2) * 2);
                uint32_t bH0 = lds32(bo), bH1 = lds32(bo + 16);
                uint32_t bL0 = lds32(bo + GB_LO), bL1 = lds32(bo + GB_LO + 16);
                #pragma unroll
                for (int mf = 0; mf < 4; mf++) {
                    float* d = acc + (mf * 8 + nf) * 4;
                    mma_bf16(d, aH[mf*4], aH[mf*4+1], aH[mf*4+2], aH[mf*4+3], bH0, bH1);
                    mma_bf16(d, aL[mf*4], aL[mf*4+1], aL[mf*4+2], aL[mf*4+3], bH0, bH1);
                    mma_bf16(d, aH[mf*4], aH[mf*4+1], aH[mf*4+2], aH[mf*4+3], bL0, bL1);
                }
            }
        }
        __syncthreads();
        if (c + 2 < 8) {
            const char* hp = (const char*)&d_Wg1t[0][c + 2][0];
            const char* lp = (const char*)&d_Wg1t[1][c + 2][0];
            uint32_t dst = smb + GB_BASE + (c & 1) * GB_STRIDE;
            #pragma unroll
            for (int it = 0; it < 5; it++) {
                int o = (tid + it * 256) * 16;
                cp16(dst + o, hp + o);
                cp16(dst + GB_LO + o, lp + o);
            }
            CP_COMMIT();
        }
    }

    #pragma unroll
    for (int mf = 0; mf < 4; mf++) {
        float p0 = 0.f, p1 = 0.f;
        #pragma unroll
        for (int nf = 0; nf < 8; nf++) {
            int idx = (mf * 8 + nf) * 4;
            int c = Cb + nf * 8 + m * 2;
            float w0 = wsv[c], w1 = wsv[c + 1];
            p0 += fmaxf(acc[idx+0] + bg1s[c],     0.f) * w0
                + fmaxf(acc[idx+1] + bg1s[c + 1], 0.f) * w1;
            p1 += fmaxf(acc[idx+2] + bg1s[c],     0.f) * w0
                + fmaxf(acc[idx+3] + bg1s[c + 1], 0.f) * w1;
        }
        p0 += __shfl_xor_sync(0xffffffffu, p0, 1);
        p0 += __shfl_xor_sync(0xffffffffu, p0, 2);
        p1 += __shfl_xor_sync(0xffffffffu, p1, 1);
        p1 += __shfl_xor_sync(0xffffffffu, p1, 2);
        if (m == 0) {
            int R = Rb + mf * 16 + q;
            rs[R * 4 + wn]       = p0;
            rs[(R + 8) * 4 + wn] = p1;
        }
    }
    __syncthreads();
    if (tid < 128) {
        int g = g0 + tid;
        if (g < num_graphs)
            out[g] = rs[tid * 4] + rs[tid * 4 + 1] + rs[tid * 4 + 2] + rs[tid * 4 + 3] + bg2[0];
    }
}

// ---------------------------------------------------------------------------
extern "C" void kernel_launch(void* const* d_in, const int* in_sizes, int n_in,
                              void* d_out, int out_size) {
    const float* h         = (const float*)d_in[0];
    const int*   graph_ids = (const int*)  d_in[1];
    const int base = (n_in >= 11) ? 3 : 2;   // skip num_graphs scalar slot if present
    const float* W1  = (const float*)d_in[base + 0];
    const float* b1  = (const float*)d_in[base + 1];
    const float* W2  = (const float*)d_in[base + 2];
    const float* b2  = (const float*)d_in[base + 3];
    const float* Wg1 = (const float*)d_in[base + 4];
    const float* bg1 = (const float*)d_in[base + 5];
    const float* Wg2 = (const float*)d_in[base + 6];
    const float* bg2 = (const float*)d_in[base + 7];
    float* out = (float*)d_out;

    const int n_atoms = in_sizes[0] / DIN;
    const int G       = out_size;            // D_OUT = 1

    static bool attrs_set = false;
    if (!attrs_set) {
        cudaFuncSetAttribute(node_kernel,
                             cudaFuncAttributeMaxDynamicSharedMemorySize, NODE_SMEM_BYTES);
        cudaFuncSetAttribute(graph_kernel,
                             cudaFuncAttributeMaxDynamicSharedMemorySize, GRAPH_SMEM_BYTES);
        attrs_set = true;
    }

    prep_kernel<<<(DIN * DH + 2 * DH * DH + 255) / 256, 256>>>(W1, W2, Wg1);
    zero_pooled_kernel<<<512, 256>>>(G * DH);

    int nblocks = (n_atoms + TILE_M - 1) / TILE_M;
    node_kernel<<<nblocks, 512, NODE_SMEM_BYTES>>>(h, graph_ids, b1, b2, n_atoms);

    int gblocks = (G + 127) / 128;
    graph_kernel<<<gblocks, 256, GRAPH_SMEM_BYTES>>>(bg1, Wg2, bg2, out, G);
}

// round 12
// speedup vs baseline: 12.4440x; 1.4634x over previous
#include <cuda_runtime.h>
#include <cuda_bf16.h>
#include <cuda_fp16.h>
#include <cstdint>

#define DIN 128
#define DH  256
#define G_MAX 20000
#define TILE_M 128

// ---------------------------------------------------------------------------
// Persistent scratch
// ---------------------------------------------------------------------------
__device__ float d_pooled[G_MAX * DH];
// W1^T (fp16), smem-image [n=256][k pad 136]
__device__ __align__(16) __half d_W1h[256 * 136];
// W2^T (fp16) in 2 K-chunks of 128: [chunk][n=256][kk pad 136]
__device__ __align__(16) __half d_W2h[2][256 * 136];
// Wg1^T hi/lo (bf16, 3-term path) in 8 K-chunks of 32: [part][chunk][n=256][kk pad 40]
__device__ __align__(16) __nv_bfloat16 d_Wg1t[2][8][256 * 40];

// ---------------------------------------------------------------------------
// helpers
// ---------------------------------------------------------------------------
__device__ __forceinline__ uint32_t smem_to_u32(const void* p) {
    uint32_t a;
    asm("{ .reg .u64 t; cvta.to.shared.u64 t, %1; cvt.u32.u64 %0, t; }" : "=r"(a) : "l"(p));
    return a;
}
__device__ __forceinline__ uint32_t lds32(uint32_t a) {
    uint32_t v;
    asm volatile("ld.shared.b32 %0, [%1];" : "=r"(v) : "r"(a));
    return v;
}
__device__ __forceinline__ void sts32(uint32_t a, uint32_t v) {
    asm volatile("st.shared.b32 [%0], %1;" :: "r"(a), "r"(v));
}
__device__ __forceinline__ void cp16(uint32_t s, const void* g) {
    asm volatile("cp.async.ca.shared.global [%0], [%1], 16;" :: "r"(s), "l"(g));
}
#define CP_COMMIT() asm volatile("cp.async.commit_group;" ::: "memory")
#define CP_WAITN(n) asm volatile("cp.async.wait_group %0;" :: "n"(n) : "memory")

// m16n8k16 fp16 inputs, fp32 accum
__device__ __forceinline__ void mma_f16(float* d, uint32_t a0, uint32_t a1, uint32_t a2,
                                        uint32_t a3, uint32_t b0, uint32_t b1) {
    asm volatile(
        "mma.sync.aligned.m16n8k16.row.col.f32.f16.f16.f32 "
        "{%0,%1,%2,%3}, {%4,%5,%6,%7}, {%8,%9}, {%0,%1,%2,%3};"
        : "+f"(d[0]), "+f"(d[1]), "+f"(d[2]), "+f"(d[3])
        : "r"(a0), "r"(a1), "r"(a2), "r"(a3), "r"(b0), "r"(b1));
}
// m16n8k16 bf16 inputs, fp32 accum (graph kernel, 3-term path)
__device__ __forceinline__ void mma_bf16(float* d, uint32_t a0, uint32_t a1, uint32_t a2,
                                         uint32_t a3, uint32_t b0, uint32_t b1) {
    asm volatile(
        "mma.sync.aligned.m16n8k16.row.col.f32.bf16.bf16.f32 "
        "{%0,%1,%2,%3}, {%4,%5,%6,%7}, {%8,%9}, {%0,%1,%2,%3};"
        : "+f"(d[0]), "+f"(d[1]), "+f"(d[2]), "+f"(d[3])
        : "r"(a0), "r"(a1), "r"(a2), "r"(a3), "r"(b0), "r"(b1));
}
// round two floats to fp16, pack to one u32
__device__ __forceinline__ uint32_t pack2h(float v0, float v1) {
    __half h0 = __float2half(v0), h1 = __float2half(v1);
    return (uint32_t)__half_as_ushort(h0) | ((uint32_t)__half_as_ushort(h1) << 16);
}
// bf16 split pack (graph kernel)
__device__ __forceinline__ uint32_t packb_hi(float v0, float v1, uint32_t& lo_out) {
    __nv_bfloat16 h0 = __float2bfloat16(v0), h1 = __float2bfloat16(v1);
    __nv_bfloat16 l0 = __float2bfloat16(v0 - __bfloat162float(h0));
    __nv_bfloat16 l1 = __float2bfloat16(v1 - __bfloat162float(h1));
    lo_out = (uint32_t)__bfloat16_as_ushort(l0) | ((uint32_t)__bfloat16_as_ushort(l1) << 16);
    return (uint32_t)__bfloat16_as_ushort(h0) | ((uint32_t)__bfloat16_as_ushort(h1) << 16);
}

// ---------------------------------------------------------------------------
// Kernel 0: zero pooled accumulator
// ---------------------------------------------------------------------------
__global__ void zero_pooled_kernel(int total) {
    int i = blockIdx.x * blockDim.x + threadIdx.x;
    int stride = gridDim.x * blockDim.x;
    for (; i < total; i += stride) d_pooled[i] = 0.0f;
}

// ---------------------------------------------------------------------------
// Kernel P: bake W1^T (fp16), W2^T (fp16), Wg1^T (bf16 hi/lo)
// ---------------------------------------------------------------------------
__global__ void prep_kernel(const float* __restrict__ W1, const float* __restrict__ W2,
                            const float* __restrict__ Wg1) {
    int idx = blockIdx.x * blockDim.x + threadIdx.x;
    if (idx < DIN * DH) {                          // W1 [k=128][n=256]
        int k = idx / DH, n = idx % DH;
        d_W1h[n * 136 + k] = __float2half(W1[idx]);
    } else if (idx < DIN * DH + DH * DH) {         // W2 [k=256][n=256]
        int i2 = idx - DIN * DH;
        int k = i2 / DH, n = i2 % DH;
        d_W2h[k >> 7][n * 136 + (k & 127)] = __float2half(W2[i2]);
    } else if (idx < DIN * DH + 2 * DH * DH) {     // Wg1 [k=256][n=256]
        int i2 = idx - DIN * DH - DH * DH;
        int k = i2 / DH, n = i2 % DH;
        float v = Wg1[i2];
        __nv_bfloat16 hi = __float2bfloat16(v);
        __nv_bfloat16 lo = __float2bfloat16(v - __bfloat162float(hi));
        d_Wg1t[0][k >> 5][n * 40 + (k & 31)] = hi;
        d_Wg1t[1][k >> 5][n * 40 + (k & 31)] = lo;
    }
}

// ---------------------------------------------------------------------------
// Kernel 1: fused node MLP via mma.sync fp16 (1-term) + segmented pool
// 512 threads (16 warps, grid 4M x 4N, 32x64 per-warp tile), 128-node tile.
// smem:
//   phase1: A1h[128][136]h @0 (34816), W1h image @34816 (69632 -> 104448)
//   phase2: A2h[128][264]h @0 (67584),
//           W2 chunk0 @67584 (69632 -> 137216), chunk1 @137216 (-> 206848)
//   epi2  : X2 fp32 [128][264] @0 (135168), aliases A2h+chunk0 after mma reads
//   aux   : b1s @206848, b2s @207872, gids @208896 -> 209408 total
// ---------------------------------------------------------------------------
#define SA1    0
#define SW1    34816
#define SA2    0
#define SW2C   67584
#define SW2STR 69632
#define SX2    0
#define SO_B1S 206848
#define SO_B2S 207872
#define SO_GID 208896
#define NODE_SMEM_BYTES 209408

extern "C" __global__ void __launch_bounds__(512, 1)
node_kernel(const float* __restrict__ h, const int* __restrict__ graph_ids,
            const float* __restrict__ b1, const float* __restrict__ b2, int n_atoms)
{
    extern __shared__ unsigned char sm[];
    const uint32_t smb = smem_to_u32(sm);
    const int tid = threadIdx.x;
    const int w   = tid >> 5;
    const int l   = tid & 31;
    const int q   = l >> 2;
    const int m   = l & 3;
    const int wm  = w >> 2;            // 0..3  (M group, 32 rows)
    const int wn  = w & 3;             // 0..3  (N group, 64 cols)
    const int Rb  = wm * 32;
    const int Cb  = wn * 64;
    const int row0 = blockIdx.x * TILE_M;

    float* b1s = (float*)(sm + SO_B1S);
    float* b2s = (float*)(sm + SO_B2S);
    int*   gids = (int*)(sm + SO_GID);

    // ---- prefetch W1 image via cp.async (group 0) ----
    {
        const char* p = (const char*)&d_W1h[0];
        for (int i = tid; i < 4352; i += 512) cp16(smb + SW1 + i * 16, p + i * 16);
        CP_COMMIT();
    }

    if (tid < 256) {
        b1s[tid] = b1[tid];
        b2s[tid] = b2[tid];
    }
    if (tid < TILE_M) {
        int r = row0 + tid;
        gids[tid] = (r < n_atoms) ? graph_ids[r] : -1;
    }

    // ---- A1: load h tile, round to fp16, [r][k] stride 136 halfs ----
    #pragma unroll 4
    for (int it = 0; it < 8; it++) {
        int idx = tid + it * 512;
        int r = idx >> 5, c = (idx & 31) * 4;
        float4 v = make_float4(0.f, 0.f, 0.f, 0.f);
        if (row0 + r < n_atoms)
            v = *(const float4*)(h + (size_t)(row0 + r) * DIN + c);
        uint32_t off = (uint32_t)(r * 136 + c) * 2;
        *(uint2*)(sm + SA1 + off) = make_uint2(pack2h(v.x, v.y), pack2h(v.z, v.w));
    }
    CP_WAITN(0);
    __syncthreads();

    float acc[64];
    #pragma unroll
    for (int i = 0; i < 64; i++) acc[i] = 0.f;

    // ================= Layer 1: K=128, 8 k-steps, 1 MMA per tile ===========
    #pragma unroll
    for (int ks = 0; ks < 8; ks++) {
        uint32_t aH[8];
        #pragma unroll
        for (int mf = 0; mf < 2; mf++) {
            uint32_t ao = smb + SA1 + (uint32_t)(((Rb + mf * 16 + q) * 136 + ks * 16 + m * 2) * 2);
            aH[mf*4+0] = lds32(ao);        aH[mf*4+1] = lds32(ao + 2176);
            aH[mf*4+2] = lds32(ao + 16);   aH[mf*4+3] = lds32(ao + 2192);
        }
        #pragma unroll
        for (int nf = 0; nf < 8; nf++) {
            uint32_t bo = smb + SW1 + (uint32_t)(((Cb + nf * 8 + q) * 136 + ks * 16 + m * 2) * 2);
            uint32_t bH0 = lds32(bo), bH1 = lds32(bo + 16);
            #pragma unroll
            for (int mf = 0; mf < 2; mf++)
                mma_f16(acc + (mf * 8 + nf) * 4,
                        aH[mf*4], aH[mf*4+1], aH[mf*4+2], aH[mf*4+3], bH0, bH1);
        }
    }
    __syncthreads();   // layer-1 reads of A1/W1 done; regions may be overwritten

    // ---- stream full W2 (2 chunks of K=128, groups 1 and 0) ----
    #pragma unroll
    for (int cc = 0; cc < 2; cc++) {
        const char* p = (const char*)&d_W2h[cc][0];
        uint32_t dst = smb + SW2C + cc * SW2STR;
        for (int i = tid; i < 4352; i += 512) cp16(dst + i * 16, p + i * 16);
        CP_COMMIT();
    }

    // ===== Epilogue 1: bias+relu, round to fp16 -> A2 [r][c] stride 264 =====
    #pragma unroll
    for (int mf = 0; mf < 2; mf++) {
        #pragma unroll
        for (int nf = 0; nf < 8; nf++) {
            int idx = (mf * 8 + nf) * 4;
            int c = Cb + nf * 8 + m * 2;
            int R = Rb + mf * 16 + q;
            float v0 = fmaxf(acc[idx+0] + b1s[c],     0.f);
            float v1 = fmaxf(acc[idx+1] + b1s[c + 1], 0.f);
            float v2 = fmaxf(acc[idx+2] + b1s[c],     0.f);
            float v3 = fmaxf(acc[idx+3] + b1s[c + 1], 0.f);
            uint32_t off = (uint32_t)((R * 264 + c) * 2);
            sts32(smb + SA2 + off, pack2h(v0, v1));
            sts32(smb + SA2 + off + 4224, pack2h(v2, v3));   // row +8
            acc[idx+0] = 0.f; acc[idx+1] = 0.f; acc[idx+2] = 0.f; acc[idx+3] = 0.f;
        }
    }

    // ========== Layer 2: K=256 in 2 halves of 128, streamed once ==========
    #pragma unroll
    for (int half = 0; half < 2; half++) {
        if (half == 0) CP_WAITN(1); else CP_WAITN(0);
        __syncthreads();   // chunk data + (half==0) A2 stores visible
        uint32_t SB = smb + SW2C + half * SW2STR;
        #pragma unroll
        for (int kk = 0; kk < 8; kk++) {
            uint32_t aH[8];
            #pragma unroll
            for (int mf = 0; mf < 2; mf++) {
                uint32_t ao = smb + SA2 + (uint32_t)(((Rb + mf * 16 + q) * 264 + half * 128 + kk * 16 + m * 2) * 2);
                aH[mf*4+0] = lds32(ao);        aH[mf*4+1] = lds32(ao + 4224);
                aH[mf*4+2] = lds32(ao + 16);   aH[mf*4+3] = lds32(ao + 4240);
            }
            #pragma unroll
            for (int nf = 0; nf < 8; nf++) {
                uint32_t bo = SB + (uint32_t)(((Cb + nf * 8 + q) * 136 + kk * 16 + m * 2) * 2);
                uint32_t bH0 = lds32(bo), bH1 = lds32(bo + 16);
                #pragma unroll
                for (int mf = 0; mf < 2; mf++)
                    mma_f16(acc + (mf * 8 + nf) * 4,
                            aH[mf*4], aH[mf*4+1], aH[mf*4+2], aH[mf*4+3], bH0, bH1);
            }
        }
    }
    __syncthreads();   // all layer-2 reads done before X2 aliases A2/chunk0

    // ===== Epilogue 2: bias+relu -> X2 fp32 [r][264] =====
    {
        float* X2 = (float*)(sm + SX2);
        #pragma unroll
        for (int mf = 0; mf < 2; mf++) {
            #pragma unroll
            for (int nf = 0; nf < 8; nf++) {
                int idx = (mf * 8 + nf) * 4;
                int c = Cb + nf * 8 + m * 2;
                int R = Rb + mf * 16 + q;
                X2[R * 264 + c]           = fmaxf(acc[idx+0] + b2s[c],     0.f);
                X2[R * 264 + c + 1]       = fmaxf(acc[idx+1] + b2s[c + 1], 0.f);
                X2[(R + 8) * 264 + c]     = fmaxf(acc[idx+2] + b2s[c],     0.f);
                X2[(R + 8) * 264 + c + 1] = fmaxf(acc[idx+3] + b2s[c + 1], 0.f);
            }
        }
    }
    __syncthreads();

    // ===== Block-local segmented sum over sorted gids, then atomics =====
    {
        const int col  = tid & 255;
        const int rlo  = (tid >> 8) * 64;
        const float* X2 = (const float*)(sm + SX2);
        int cur = -1;
        float s = 0.f;
        #pragma unroll 8
        for (int rr = 0; rr < 64; rr++) {
            int r = rlo + rr;
            int g = gids[r];
            if (g != cur) {
                if (cur >= 0) atomicAdd(&d_pooled[(size_t)cur * DH + col], s);
                cur = g;
                s = 0.f;
            }
            if (g >= 0) s += X2[r * 264 + col];
        }
        if (cur >= 0) atomicAdd(&d_pooled[(size_t)cur * DH + col], s);
    }
}

// ---------------------------------------------------------------------------
// Kernel 2: graph MLP via mma.sync split-bf16 3-term (unchanged, 56us)
// ---------------------------------------------------------------------------
#define GA_HI  0
#define GA_LO  67584
#define GB_BASE 135168
#define GB_STRIDE 40960
#define GB_LO  20480
#define GSO_BG1 217088
#define GSO_WS  218112
#define GSO_RS  219136
#define GRAPH_SMEM_BYTES 221184

extern "C" __global__ void __launch_bounds__(256, 1)
graph_kernel(const float* __restrict__ bg1, const float* __restrict__ Wg2,
             const float* __restrict__ bg2, float* __restrict__ out, int num_graphs)
{
    extern __shared__ unsigned char sm[];
    const uint32_t smb = smem_to_u32(sm);
    const int tid = threadIdx.x;
    const int l   = tid & 31;
    const int q   = l >> 2;
    const int m   = l & 3;
    const int w   = tid >> 5;
    const int wm  = w >> 2;
    const int wn  = w & 3;
    const int Rb  = wm * 64;
    const int Cb  = wn * 64;
    const int g0  = blockIdx.x * 128;

    float* bg1s = (float*)(sm + GSO_BG1);
    float* wsv  = (float*)(sm + GSO_WS);
    float* rs   = (float*)(sm + GSO_RS);

    #pragma unroll
    for (int cc = 0; cc < 2; cc++) {
        const char* hp = (const char*)&d_Wg1t[0][cc][0];
        const char* lp = (const char*)&d_Wg1t[1][cc][0];
        uint32_t dst = smb + GB_BASE + cc * GB_STRIDE;
        #pragma unroll
        for (int it = 0; it < 5; it++) {
            int o = (tid + it * 256) * 16;
            cp16(dst + o, hp + o);
            cp16(dst + GB_LO + o, lp + o);
        }
        CP_COMMIT();
    }

    bg1s[tid] = bg1[tid];
    wsv[tid]  = Wg2[tid];

    #pragma unroll 4
    for (int it = 0; it < 32; it++) {
        int idx = tid + it * 256;
        int r = idx >> 6, c = (idx & 63) * 4;
        float4 v = make_float4(0.f, 0.f, 0.f, 0.f);
        if (g0 + r < num_graphs)
            v = *(const float4*)(d_pooled + (size_t)(g0 + r) * DH + c);
        uint32_t lo0, lo1;
        uint32_t hi0 = packb_hi(v.x, v.y, lo0);
        uint32_t hi1 = packb_hi(v.z, v.w, lo1);
        uint32_t off = (uint32_t)(r * 264 + c) * 2;
        *(uint2*)(sm + GA_HI + off) = make_uint2(hi0, hi1);
        *(uint2*)(sm + GA_LO + off) = make_uint2(lo0, lo1);
    }

    float acc[128];
    #pragma unroll
    for (int i = 0; i < 128; i++) acc[i] = 0.f;

    for (int c = 0; c < 8; c++) {
        if (c < 7) CP_WAITN(1); else CP_WAITN(0);
        __syncthreads();
        uint32_t SB = smb + GB_BASE + (c & 1) * GB_STRIDE;
        #pragma unroll
        for (int ks = 0; ks < 2; ks++) {
            uint32_t aH[16], aL[16];
            #pragma unroll
            for (int mf = 0; mf < 4; mf++) {
                uint32_t ao = smb + (uint32_t)(((Rb + mf * 16 + q) * 264 + c * 32 + ks * 16 + m * 2) * 2);
                aH[mf*4+0] = lds32(ao + GA_HI);        aH[mf*4+1] = lds32(ao + GA_HI + 4224);
                aH[mf*4+2] = lds32(ao + GA_HI + 16);   aH[mf*4+3] = lds32(ao + GA_HI + 4240);
                aL[mf*4+0] = lds32(ao + GA_LO);        aL[mf*4+1] = lds32(ao + GA_LO + 4224);
                aL[mf*4+2] = lds32(ao + GA_LO + 16);   aL[mf*4+3] = lds32(ao + GA_LO + 4240);
            }
            #pragma unroll
            for (int nf = 0; nf < 8; nf++) {
                uint32_t bo = SB + (uint32_t)(((Cb + nf * 8 + q) * 40 + ks * 16 + m * 2) * 2);
                uint32_t bH0 = lds32(bo), bH1 = lds32(bo + 16);
                uint32_t bL0 = lds32(bo + GB_LO), bL1 = lds32(bo + GB_LO + 16);
                #pragma unroll
                for (int mf = 0; mf < 4; mf++) {
                    float* d = acc + (mf * 8 + nf) * 4;
                    mma_bf16(d, aH[mf*4], aH[mf*4+1], aH[mf*4+2], aH[mf*4+3], bH0, bH1);
                    mma_bf16(d, aL[mf*4], aL[mf*4+1], aL[mf*4+2], aL[mf*4+3], bH0, bH1);
                    mma_bf16(d, aH[mf*4], aH[mf*4+1], aH[mf*4+2], aH[mf*4+3], bL0, bL1);
                }
            }
        }
        __syncthreads();
        if (c + 2 < 8) {
            const char* hp = (const char*)&d_Wg1t[0][c + 2][0];
            const char* lp = (const char*)&d_Wg1t[1][c + 2][0];
            uint32_t dst = smb + GB_BASE + (c & 1) * GB_STRIDE;
            #pragma unroll
            for (int it = 0; it < 5; it++) {
                int o = (tid + it * 256) * 16;
                cp16(dst + o, hp + o);
                cp16(dst + GB_LO + o, lp + o);
            }
            CP_COMMIT();
        }
    }

    #pragma unroll
    for (int mf = 0; mf < 4; mf++) {
        float p0 = 0.f, p1 = 0.f;
        #pragma unroll
        for (int nf = 0; nf < 8; nf++) {
            int idx = (mf * 8 + nf) * 4;
            int c = Cb + nf * 8 + m * 2;
            float w0 = wsv[c], w1 = wsv[c + 1];
            p0 += fmaxf(acc[idx+0] + bg1s[c],     0.f) * w0
                + fmaxf(acc[idx+1] + bg1s[c + 1], 0.f) * w1;
            p1 += fmaxf(acc[idx+2] + bg1s[c],     0.f) * w0
                + fmaxf(acc[idx+3] + bg1s[c + 1], 0.f) * w1;
        }
        p0 += __shfl_xor_sync(0xffffffffu, p0, 1);
        p0 += __shfl_xor_sync(0xffffffffu, p0, 2);
        p1 += __shfl_xor_sync(0xffffffffu, p1, 1);
        p1 += __shfl_xor_sync(0xffffffffu, p1, 2);
        if (m == 0) {
            int R = Rb + mf * 16 + q;
            rs[R * 4 + wn]       = p0;
            rs[(R + 8) * 4 + wn] = p1;
        }
    }
    __syncthreads();
    if (tid < 128) {
        int g = g0 + tid;
        if (g < num_graphs)
            out[g] = rs[tid * 4] + rs[tid * 4 + 1] + rs[tid * 4 + 2] + rs[tid * 4 + 3] + bg2[0];
    }
}

// ---------------------------------------------------------------------------
extern "C" void kernel_launch(void* const* d_in, const int* in_sizes, int n_in,
                              void* d_out, int out_size) {
    const float* h         = (const float*)d_in[0];
    const int*   graph_ids = (const int*)  d_in[1];
    const int base = (n_in >= 11) ? 3 : 2;   // skip num_graphs scalar slot if present
    const float* W1  = (const float*)d_in[base + 0];
    const float* b1  = (const float*)d_in[base + 1];
    const float* W2  = (const float*)d_in[base + 2];
    const float* b2  = (const float*)d_in[base + 3];
    const float* Wg1 = (const float*)d_in[base + 4];
    const float* bg1 = (const float*)d_in[base + 5];
    const float* Wg2 = (const float*)d_in[base + 6];
    const float* bg2 = (const float*)d_in[base + 7];
    float* out = (float*)d_out;

    const int n_atoms = in_sizes[0] / DIN;
    const int G       = out_size;            // D_OUT = 1

    static bool attrs_set = false;
    if (!attrs_set) {
        cudaFuncSetAttribute(node_kernel,
                             cudaFuncAttributeMaxDynamicSharedMemorySize, NODE_SMEM_BYTES);
        cudaFuncSetAttribute(graph_kernel,
                             cudaFuncAttributeMaxDynamicSharedMemorySize, GRAPH_SMEM_BYTES);
        attrs_set = true;
    }

    prep_kernel<<<(DIN * DH + 2 * DH * DH + 255) / 256, 256>>>(W1, W2, Wg1);
    zero_pooled_kernel<<<512, 256>>>(G * DH);

    int nblocks = (n_atoms + TILE_M - 1) / TILE_M;
    node_kernel<<<nblocks, 512, NODE_SMEM_BYTES>>>(h, graph_ids, b1, b2, n_atoms);

    int gblocks = (G + 127) / 128;
    graph_kernel<<<gblocks, 256, GRAPH_SMEM_BYTES>>>(bg1, Wg2, bg2, out, G);
}

// round 13
// speedup vs baseline: 13.3469x; 1.0726x over previous
#include <cuda_runtime.h>
#include <cuda_bf16.h>
#include <cuda_fp16.h>
#include <cstdint>

#define DIN 128
#define DH  256
#define G_MAX 20000
#define TILE_M 128

// ---------------------------------------------------------------------------
// Persistent scratch
// ---------------------------------------------------------------------------
__device__ float d_pooled[G_MAX * DH];
// W1^T (fp16), smem-image [n=256][k pad 136]
__device__ __align__(16) __half d_W1h[256 * 136];
// W2^T (fp16) in 2 K-chunks of 128: [chunk][n=256][kk pad 136]
__device__ __align__(16) __half d_W2h[2][256 * 136];
// Wg1^T (fp16) in 2 K-chunks of 128: [chunk][n=256][kk pad 136]
__device__ __align__(16) __half d_Wg1h[2][256 * 136];

// ---------------------------------------------------------------------------
// helpers
// ---------------------------------------------------------------------------
__device__ __forceinline__ uint32_t smem_to_u32(const void* p) {
    uint32_t a;
    asm("{ .reg .u64 t; cvta.to.shared.u64 t, %1; cvt.u32.u64 %0, t; }" : "=r"(a) : "l"(p));
    return a;
}
__device__ __forceinline__ void sts32(uint32_t a, uint32_t v) {
    asm volatile("st.shared.b32 [%0], %1;" :: "r"(a), "r"(v));
}
__device__ __forceinline__ void cp16(uint32_t s, const void* g) {
    asm volatile("cp.async.ca.shared.global [%0], [%1], 16;" :: "r"(s), "l"(g));
}
#define CP_COMMIT() asm volatile("cp.async.commit_group;" ::: "memory")
#define CP_WAITN(n) asm volatile("cp.async.wait_group %0;" :: "n"(n) : "memory")

// ldmatrix x4: four 8x8 b16 tiles
__device__ __forceinline__ void ldsm4(uint32_t& r0, uint32_t& r1, uint32_t& r2, uint32_t& r3,
                                      uint32_t addr) {
    asm volatile("ldmatrix.sync.aligned.m8n8.x4.shared.b16 {%0,%1,%2,%3}, [%4];"
                 : "=r"(r0), "=r"(r1), "=r"(r2), "=r"(r3) : "r"(addr));
}
// m16n8k16 fp16 inputs, fp32 accum
__device__ __forceinline__ void mma_f16(float* d, uint32_t a0, uint32_t a1, uint32_t a2,
                                        uint32_t a3, uint32_t b0, uint32_t b1) {
    asm volatile(
        "mma.sync.aligned.m16n8k16.row.col.f32.f16.f16.f32 "
        "{%0,%1,%2,%3}, {%4,%5,%6,%7}, {%8,%9}, {%0,%1,%2,%3};"
        : "+f"(d[0]), "+f"(d[1]), "+f"(d[2]), "+f"(d[3])
        : "r"(a0), "r"(a1), "r"(a2), "r"(a3), "r"(b0), "r"(b1));
}
// round two floats to fp16, pack to one u32
__device__ __forceinline__ uint32_t pack2h(float v0, float v1) {
    __half h0 = __float2half(v0), h1 = __float2half(v1);
    return (uint32_t)__half_as_ushort(h0) | ((uint32_t)__half_as_ushort(h1) << 16);
}

// ---------------------------------------------------------------------------
// Kernel 0: zero pooled accumulator
// ---------------------------------------------------------------------------
__global__ void zero_pooled_kernel(int total) {
    int i = blockIdx.x * blockDim.x + threadIdx.x;
    int stride = gridDim.x * blockDim.x;
    for (; i < total; i += stride) d_pooled[i] = 0.0f;
}

// ---------------------------------------------------------------------------
// Kernel P: bake W1^T / W2^T / Wg1^T into fp16 images
// ---------------------------------------------------------------------------
__global__ void prep_kernel(const float* __restrict__ W1, const float* __restrict__ W2,
                            const float* __restrict__ Wg1) {
    int idx = blockIdx.x * blockDim.x + threadIdx.x;
    if (idx < DIN * DH) {                          // W1 [k=128][n=256]
        int k = idx / DH, n = idx % DH;
        d_W1h[n * 136 + k] = __float2half(W1[idx]);
    } else if (idx < DIN * DH + DH * DH) {         // W2 [k=256][n=256]
        int i2 = idx - DIN * DH;
        int k = i2 / DH, n = i2 % DH;
        d_W2h[k >> 7][n * 136 + (k & 127)] = __float2half(W2[i2]);
    } else if (idx < DIN * DH + 2 * DH * DH) {     // Wg1 [k=256][n=256]
        int i2 = idx - DIN * DH - DH * DH;
        int k = i2 / DH, n = i2 % DH;
        d_Wg1h[k >> 7][n * 136 + (k & 127)] = __float2half(Wg1[i2]);
    }
}

// ---------------------------------------------------------------------------
// Kernel 1: fused node MLP via mma.sync fp16 + ldmatrix + segmented pool
// 512 threads (16 warps, grid 4M x 4N, 32x64 per-warp tile), 128-node tile.
// smem layout identical to R12 (209408 B).
// ---------------------------------------------------------------------------
#define SA1    0
#define SW1    34816
#define SA2    0
#define SW2C   67584
#define SW2STR 69632
#define SX2    0
#define SO_B1S 206848
#define SO_B2S 207872
#define SO_GID 208896
#define NODE_SMEM_BYTES 209408

extern "C" __global__ void __launch_bounds__(512, 1)
node_kernel(const float* __restrict__ h, const int* __restrict__ graph_ids,
            const float* __restrict__ b1, const float* __restrict__ b2, int n_atoms)
{
    extern __shared__ unsigned char sm[];
    const uint32_t smb = smem_to_u32(sm);
    const int tid = threadIdx.x;
    const int w   = tid >> 5;
    const int l   = tid & 31;
    const int q   = l >> 2;
    const int m   = l & 3;
    const int wm  = w >> 2;            // 0..3  (M group, 32 rows)
    const int wn  = w & 3;             // 0..3  (N group, 64 cols)
    const int Rb  = wm * 32;
    const int Cb  = wn * 64;
    const int row0 = blockIdx.x * TILE_M;

    // ldmatrix per-lane address components
    const int aRow  = l & 15;           // row within 16-row A tile
    const int aKoff = (l >> 4) * 8;     // k-half select
    const int bN    = (l >> 4) * 8 + (l & 7);   // n within 16-col B pair
    const int bKoff = ((l >> 3) & 1) * 8;       // k-half select

    float* b1s = (float*)(sm + SO_B1S);
    float* b2s = (float*)(sm + SO_B2S);
    int*   gids = (int*)(sm + SO_GID);

    // ---- prefetch W1 image via cp.async (group 0) ----
    {
        const char* p = (const char*)&d_W1h[0];
        for (int i = tid; i < 4352; i += 512) cp16(smb + SW1 + i * 16, p + i * 16);
        CP_COMMIT();
    }

    if (tid < 256) {
        b1s[tid] = b1[tid];
        b2s[tid] = b2[tid];
    }
    if (tid < TILE_M) {
        int r = row0 + tid;
        gids[tid] = (r < n_atoms) ? graph_ids[r] : -1;
    }

    // ---- A1: load h tile, round to fp16, [r][k] stride 136 halfs ----
    #pragma unroll 4
    for (int it = 0; it < 8; it++) {
        int idx = tid + it * 512;
        int r = idx >> 5, c = (idx & 31) * 4;
        float4 v = make_float4(0.f, 0.f, 0.f, 0.f);
        if (row0 + r < n_atoms)
            v = *(const float4*)(h + (size_t)(row0 + r) * DIN + c);
        uint32_t off = (uint32_t)(r * 136 + c) * 2;
        *(uint2*)(sm + SA1 + off) = make_uint2(pack2h(v.x, v.y), pack2h(v.z, v.w));
    }
    CP_WAITN(0);
    __syncthreads();

    float acc[64];
    #pragma unroll
    for (int i = 0; i < 64; i++) acc[i] = 0.f;

    // ================= Layer 1: K=128, 8 k-steps, ldmatrix operands ========
    {
        const uint32_t aBase = smb + SA1 + (uint32_t)(((Rb + aRow) * 136 + aKoff) * 2);
        const uint32_t bBase = smb + SW1 + (uint32_t)(((Cb + bN) * 136 + bKoff) * 2);
        #pragma unroll
        for (int ks = 0; ks < 8; ks++) {
            uint32_t aH[8];
            ldsm4(aH[0], aH[1], aH[2], aH[3], aBase + ks * 32);
            ldsm4(aH[4], aH[5], aH[6], aH[7], aBase + 16 * 272 + ks * 32);
            #pragma unroll
            for (int nfp = 0; nfp < 4; nfp++) {
                uint32_t b0a, b1a, b0b, b1b;
                ldsm4(b0a, b1a, b0b, b1b, bBase + nfp * 16 * 272 + ks * 32);
                #pragma unroll
                for (int mf = 0; mf < 2; mf++) {
                    mma_f16(acc + (mf * 8 + nfp * 2) * 4,
                            aH[mf*4], aH[mf*4+1], aH[mf*4+2], aH[mf*4+3], b0a, b1a);
                    mma_f16(acc + (mf * 8 + nfp * 2 + 1) * 4,
                            aH[mf*4], aH[mf*4+1], aH[mf*4+2], aH[mf*4+3], b0b, b1b);
                }
            }
        }
    }
    __syncthreads();   // layer-1 reads of A1/W1 done; regions may be overwritten

    // ---- stream full W2 (2 chunks of K=128, groups 1 and 0) ----
    #pragma unroll
    for (int cc = 0; cc < 2; cc++) {
        const char* p = (const char*)&d_W2h[cc][0];
        uint32_t dst = smb + SW2C + cc * SW2STR;
        for (int i = tid; i < 4352; i += 512) cp16(dst + i * 16, p + i * 16);
        CP_COMMIT();
    }

    // ===== Epilogue 1: bias+relu, round to fp16 -> A2 [r][c] stride 264 =====
    #pragma unroll
    for (int mf = 0; mf < 2; mf++) {
        #pragma unroll
        for (int nf = 0; nf < 8; nf++) {
            int idx = (mf * 8 + nf) * 4;
            int c = Cb + nf * 8 + m * 2;
            int R = Rb + mf * 16 + q;
            float v0 = fmaxf(acc[idx+0] + b1s[c],     0.f);
            float v1 = fmaxf(acc[idx+1] + b1s[c + 1], 0.f);
            float v2 = fmaxf(acc[idx+2] + b1s[c],     0.f);
            float v3 = fmaxf(acc[idx+3] + b1s[c + 1], 0.f);
            uint32_t off = (uint32_t)((R * 264 + c) * 2);
            sts32(smb + SA2 + off, pack2h(v0, v1));
            sts32(smb + SA2 + off + 4224, pack2h(v2, v3));   // row +8
            acc[idx+0] = 0.f; acc[idx+1] = 0.f; acc[idx+2] = 0.f; acc[idx+3] = 0.f;
        }
    }

    // ========== Layer 2: K=256 in 2 halves of 128, streamed once ==========
    {
        const uint32_t aBase2 = smb + SA2 + (uint32_t)(((Rb + aRow) * 264 + aKoff) * 2);
        #pragma unroll
        for (int half = 0; half < 2; half++) {
            if (half == 0) CP_WAITN(1); else CP_WAITN(0);
            __syncthreads();   // chunk data + (half==0) A2 stores visible
            const uint32_t bBase2 = smb + SW2C + half * SW2STR
                                  + (uint32_t)(((Cb + bN) * 136 + bKoff) * 2);
            #pragma unroll
            for (int kk = 0; kk < 8; kk++) {
                uint32_t aH[8];
                ldsm4(aH[0], aH[1], aH[2], aH[3], aBase2 + half * 256 + kk * 32);
                ldsm4(aH[4], aH[5], aH[6], aH[7], aBase2 + 16 * 528 + half * 256 + kk * 32);
                #pragma unroll
                for (int nfp = 0; nfp < 4; nfp++) {
                    uint32_t b0a, b1a, b0b, b1b;
                    ldsm4(b0a, b1a, b0b, b1b, bBase2 + nfp * 16 * 272 + kk * 32);
                    #pragma unroll
                    for (int mf = 0; mf < 2; mf++) {
                        mma_f16(acc + (mf * 8 + nfp * 2) * 4,
                                aH[mf*4], aH[mf*4+1], aH[mf*4+2], aH[mf*4+3], b0a, b1a);
                        mma_f16(acc + (mf * 8 + nfp * 2 + 1) * 4,
                                aH[mf*4], aH[mf*4+1], aH[mf*4+2], aH[mf*4+3], b0b, b1b);
                    }
                }
            }
        }
    }
    __syncthreads();   // all layer-2 reads done before X2 aliases A2/chunk0

    // ===== Epilogue 2: bias+relu -> X2 fp32 [r][264] =====
    {
        float* X2 = (float*)(sm + SX2);
        #pragma unroll
        for (int mf = 0; mf < 2; mf++) {
            #pragma unroll
            for (int nf = 0; nf < 8; nf++) {
                int idx = (mf * 8 + nf) * 4;
                int c = Cb + nf * 8 + m * 2;
                int R = Rb + mf * 16 + q;
                X2[R * 264 + c]           = fmaxf(acc[idx+0] + b2s[c],     0.f);
                X2[R * 264 + c + 1]       = fmaxf(acc[idx+1] + b2s[c + 1], 0.f);
                X2[(R + 8) * 264 + c]     = fmaxf(acc[idx+2] + b2s[c],     0.f);
                X2[(R + 8) * 264 + c + 1] = fmaxf(acc[idx+3] + b2s[c + 1], 0.f);
            }
        }
    }
    __syncthreads();

    // ===== Block-local segmented sum over sorted gids, then atomics =====
    {
        const int col  = tid & 255;
        const int rlo  = (tid >> 8) * 64;
        const float* X2 = (const float*)(sm + SX2);
        int cur = -1;
        float s = 0.f;
        #pragma unroll 8
        for (int rr = 0; rr < 64; rr++) {
            int r = rlo + rr;
            int g = gids[r];
            if (g != cur) {
                if (cur >= 0) atomicAdd(&d_pooled[(size_t)cur * DH + col], s);
                cur = g;
                s = 0.f;
            }
            if (g >= 0) s += X2[r * 264 + col];
        }
        if (cur >= 0) atomicAdd(&d_pooled[(size_t)cur * DH + col], s);
    }
}

// ---------------------------------------------------------------------------
// Kernel 2: graph MLP via mma.sync fp16 (1-term) + ldmatrix
// 256 threads (8 warps, 2M x 4N grid, 64x64 per-warp tile), 128-graph tile.
// smem: A[128][264]h @0 (67584), Wg1 chunk0 @67584, chunk1 @137216 (->206848),
//       bg1s @206848, wsv @207872, rs @208896 -> 210944
// ---------------------------------------------------------------------------
#define GA     0
#define GW     67584
#define GWSTR  69632
#define GSO_BG1 206848
#define GSO_WS  207872
#define GSO_RS  208896
#define GRAPH_SMEM_BYTES 210944

extern "C" __global__ void __launch_bounds__(256, 1)
graph_kernel(const float* __restrict__ bg1, const float* __restrict__ Wg2,
             const float* __restrict__ bg2, float* __restrict__ out, int num_graphs)
{
    extern __shared__ unsigned char sm[];
    const uint32_t smb = smem_to_u32(sm);
    const int tid = threadIdx.x;
    const int l   = tid & 31;
    const int q   = l >> 2;
    const int m   = l & 3;
    const int w   = tid >> 5;
    const int wm  = w >> 2;            // 0..1  (64 rows)
    const int wn  = w & 3;             // 0..3  (64 cols)
    const int Rb  = wm * 64;
    const int Cb  = wn * 64;
    const int g0  = blockIdx.x * 128;

    const int aRow  = l & 15;
    const int aKoff = (l >> 4) * 8;
    const int bN    = (l >> 4) * 8 + (l & 7);
    const int bKoff = ((l >> 3) & 1) * 8;

    float* bg1s = (float*)(sm + GSO_BG1);
    float* wsv  = (float*)(sm + GSO_WS);
    float* rs   = (float*)(sm + GSO_RS);

    // prefetch Wg1 chunks 0,1
    #pragma unroll
    for (int cc = 0; cc < 2; cc++) {
        const char* p = (const char*)&d_Wg1h[cc][0];
        uint32_t dst = smb + GW + cc * GWSTR;
        for (int i = tid; i < 4352; i += 256) cp16(dst + i * 16, p + i * 16);
        CP_COMMIT();
    }

    bg1s[tid] = bg1[tid];
    wsv[tid]  = Wg2[tid];

    // ---- A: load pooled tile, round to fp16, [r][c] stride 264 halfs ----
    #pragma unroll 4
    for (int it = 0; it < 32; it++) {
        int idx = tid + it * 256;
        int r = idx >> 6, c = (idx & 63) * 4;
        float4 v = make_float4(0.f, 0.f, 0.f, 0.f);
        if (g0 + r < num_graphs)
            v = *(const float4*)(d_pooled + (size_t)(g0 + r) * DH + c);
        uint32_t off = (uint32_t)(r * 264 + c) * 2;
        *(uint2*)(sm + GA + off) = make_uint2(pack2h(v.x, v.y), pack2h(v.z, v.w));
    }

    float acc[128];
    #pragma unroll
    for (int i = 0; i < 128; i++) acc[i] = 0.f;

    // ======== GEMM: K=256 in 2 halves of 128 ========
    {
        const uint32_t aBase = smb + GA + (uint32_t)(((Rb + aRow) * 264 + aKoff) * 2);
        #pragma unroll
        for (int half = 0; half < 2; half++) {
            if (half == 0) CP_WAITN(1); else CP_WAITN(0);
            __syncthreads();
            const uint32_t bBase = smb + GW + half * GWSTR
                                 + (uint32_t)(((Cb + bN) * 136 + bKoff) * 2);
            #pragma unroll
            for (int kk = 0; kk < 8; kk++) {
                uint32_t aH[16];
                #pragma unroll
                for (int mf = 0; mf < 4; mf++)
                    ldsm4(aH[mf*4], aH[mf*4+1], aH[mf*4+2], aH[mf*4+3],
                          aBase + mf * 16 * 528 + half * 256 + kk * 32);
                #pragma unroll
                for (int nfp = 0; nfp < 4; nfp++) {
                    uint32_t b0a, b1a, b0b, b1b;
                    ldsm4(b0a, b1a, b0b, b1b, bBase + nfp * 16 * 272 + kk * 32);
                    #pragma unroll
                    for (int mf = 0; mf < 4; mf++) {
                        mma_f16(acc + (mf * 8 + nfp * 2) * 4,
                                aH[mf*4], aH[mf*4+1], aH[mf*4+2], aH[mf*4+3], b0a, b1a);
                        mma_f16(acc + (mf * 8 + nfp * 2 + 1) * 4,
                                aH[mf*4], aH[mf*4+1], aH[mf*4+2], aH[mf*4+3], b0b, b1b);
                    }
                }
            }
        }
    }

    // ===== Epilogue: relu + dot with Wg2, warp reduce, rowsum smem =====
    #pragma unroll
    for (int mf = 0; mf < 4; mf++) {
        float p0 = 0.f, p1 = 0.f;
        #pragma unroll
        for (int nf = 0; nf < 8; nf++) {
            int idx = (mf * 8 + nf) * 4;
            int c = Cb + nf * 8 + m * 2;
            float w0 = wsv[c], w1 = wsv[c + 1];
            p0 += fmaxf(acc[idx+0] + bg1s[c],     0.f) * w0
                + fmaxf(acc[idx+1] + bg1s[c + 1], 0.f) * w1;
            p1 += fmaxf(acc[idx+2] + bg1s[c],     0.f) * w0
                + fmaxf(acc[idx+3] + bg1s[c + 1], 0.f) * w1;
        }
        p0 += __shfl_xor_sync(0xffffffffu, p0, 1);
        p0 += __shfl_xor_sync(0xffffffffu, p0, 2);
        p1 += __shfl_xor_sync(0xffffffffu, p1, 1);
        p1 += __shfl_xor_sync(0xffffffffu, p1, 2);
        if (m == 0) {
            int R = Rb + mf * 16 + q;
            rs[R * 4 + wn]       = p0;
            rs[(R + 8) * 4 + wn] = p1;
        }
    }
    __syncthreads();
    if (tid < 128) {
        int g = g0 + tid;
        if (g < num_graphs)
            out[g] = rs[tid * 4] + rs[tid * 4 + 1] + rs[tid * 4 + 2] + rs[tid * 4 + 3] + bg2[0];
    }
}

// ---------------------------------------------------------------------------
extern "C" void kernel_launch(void* const* d_in, const int* in_sizes, int n_in,
                              void* d_out, int out_size) {
    const float* h         = (const float*)d_in[0];
    const int*   graph_ids = (const int*)  d_in[1];
    const int base = (n_in >= 11) ? 3 : 2;   // skip num_graphs scalar slot if present
    const float* W1  = (const float*)d_in[base + 0];
    const float* b1  = (const float*)d_in[base + 1];
    const float* W2  = (const float*)d_in[base + 2];
    const float* b2  = (const float*)d_in[base + 3];
    const float* Wg1 = (const float*)d_in[base + 4];
    const float* bg1 = (const float*)d_in[base + 5];
    const float* Wg2 = (const float*)d_in[base + 6];
    const float* bg2 = (const float*)d_in[base + 7];
    float* out = (float*)d_out;

    const int n_atoms = in_sizes[0] / DIN;
    const int G       = out_size;            // D_OUT = 1

    static bool attrs_set = false;
    if (!attrs_set) {
        cudaFuncSetAttribute(node_kernel,
                             cudaFuncAttributeMaxDynamicSharedMemorySize, NODE_SMEM_BYTES);
        cudaFuncSetAttribute(graph_kernel,
                             cudaFuncAttributeMaxDynamicSharedMemorySize, GRAPH_SMEM_BYTES);
        attrs_set = true;
    }

    prep_kernel<<<(DIN * DH + 2 * DH * DH + 255) / 256, 256>>>(W1, W2, Wg1);
    zero_pooled_kernel<<<512, 256>>>(G * DH);

    int nblocks = (n_atoms + TILE_M - 1) / TILE_M;
    node_kernel<<<nblocks, 512, NODE_SMEM_BYTES>>>(h, graph_ids, b1, b2, n_atoms);

    int gblocks = (G + 127) / 128;
    graph_kernel<<<gblocks, 256, GRAPH_SMEM_BYTES>>>(bg1, Wg2, bg2, out, G);
}

// round 15
// speedup vs baseline: 14.0297x; 1.0512x over previous
#include <cuda_runtime.h>
#include <cuda_bf16.h>
#include <cuda_fp16.h>
#include <cstdint>

#define DIN 128
#define DH  256
#define G_MAX 20000
#define TILE 64

// ---------------------------------------------------------------------------
// Persistent scratch
// ---------------------------------------------------------------------------
__device__ float d_pooled[G_MAX * DH];
// W1^T (fp16), smem-image [n=256][k pad 136]
__device__ __align__(16) __half d_W1h[256 * 136];
// W2^T (fp16) in 4 K-chunks of 64: [chunk][n=256][kk pad 72]
__device__ __align__(16) __half d_W2h[4][256 * 72];
// Wg1^T (fp16) in 2 K-chunks of 128: [chunk][n=256][kk pad 136]
__device__ __align__(16) __half d_Wg1h[2][256 * 136];

// ---------------------------------------------------------------------------
// helpers
// ---------------------------------------------------------------------------
__device__ __forceinline__ uint32_t smem_to_u32(const void* p) {
    uint32_t a;
    asm("{ .reg .u64 t; cvta.to.shared.u64 t, %1; cvt.u32.u64 %0, t; }" : "=r"(a) : "l"(p));
    return a;
}
__device__ __forceinline__ void sts32(uint32_t a, uint32_t v) {
    asm volatile("st.shared.b32 [%0], %1;" :: "r"(a), "r"(v));
}
__device__ __forceinline__ void cp16(uint32_t s, const void* g) {
    asm volatile("cp.async.ca.shared.global [%0], [%1], 16;" :: "r"(s), "l"(g));
}
#define CP_COMMIT() asm volatile("cp.async.commit_group;" ::: "memory")
#define CP_WAITN(n) asm volatile("cp.async.wait_group %0;" :: "n"(n) : "memory")

// ldmatrix x4: four 8x8 b16 tiles
__device__ __forceinline__ void ldsm4(uint32_t& r0, uint32_t& r1, uint32_t& r2, uint32_t& r3,
                                      uint32_t addr) {
    asm volatile("ldmatrix.sync.aligned.m8n8.x4.shared.b16 {%0,%1,%2,%3}, [%4];"
                 : "=r"(r0), "=r"(r1), "=r"(r2), "=r"(r3) : "r"(addr));
}
// m16n8k16 fp16 inputs, fp32 accum
__device__ __forceinline__ void mma_f16(float* d, uint32_t a0, uint32_t a1, uint32_t a2,
                                        uint32_t a3, uint32_t b0, uint32_t b1) {
    asm volatile(
        "mma.sync.aligned.m16n8k16.row.col.f32.f16.f16.f32 "
        "{%0,%1,%2,%3}, {%4,%5,%6,%7}, {%8,%9}, {%0,%1,%2,%3};"
        : "+f"(d[0]), "+f"(d[1]), "+f"(d[2]), "+f"(d[3])
        : "r"(a0), "r"(a1), "r"(a2), "r"(a3), "r"(b0), "r"(b1));
}
// round two floats to fp16, pack to one u32
__device__ __forceinline__ uint32_t pack2h(float v0, float v1) {
    __half h0 = __float2half(v0), h1 = __float2half(v1);
    return (uint32_t)__half_as_ushort(h0) | ((uint32_t)__half_as_ushort(h1) << 16);
}

// ---------------------------------------------------------------------------
// Kernel 0: zero pooled accumulator
// ---------------------------------------------------------------------------
__global__ void zero_pooled_kernel(int total) {
    int i = blockIdx.x * blockDim.x + threadIdx.x;
    int stride = gridDim.x * blockDim.x;
    for (; i < total; i += stride) d_pooled[i] = 0.0f;
}

// ---------------------------------------------------------------------------
// Kernel P: bake W1^T / W2^T / Wg1^T into fp16 images
// ---------------------------------------------------------------------------
__global__ void prep_kernel(const float* __restrict__ W1, const float* __restrict__ W2,
                            const float* __restrict__ Wg1) {
    int idx = blockIdx.x * blockDim.x + threadIdx.x;
    if (idx < DIN * DH) {                          // W1 [k=128][n=256]
        int k = idx / DH, n = idx % DH;
        d_W1h[n * 136 + k] = __float2half(W1[idx]);
    } else if (idx < DIN * DH + DH * DH) {         // W2 [k=256][n=256]
        int i2 = idx - DIN * DH;
        int k = i2 / DH, n = i2 % DH;
        d_W2h[k >> 6][n * 72 + (k & 63)] = __float2half(W2[i2]);
    } else if (idx < DIN * DH + 2 * DH * DH) {     // Wg1 [k=256][n=256]
        int i2 = idx - DIN * DH - DH * DH;
        int k = i2 / DH, n = i2 % DH;
        d_Wg1h[k >> 7][n * 136 + (k & 127)] = __float2half(Wg1[i2]);
    }
}

// ---------------------------------------------------------------------------
// Kernel 1: fused node MLP, fp16 mma + ldmatrix, 64-node tile, 2 CTAs/SM.
// 256 threads (8 warps, grid 2M x 4N, 32x64 per-warp tile).
// smem (107 KB):
//   phase1: A1h[64][136] @0 (17408), W1 image @17408 (69632 -> 87040)
//   phase2: A2h[64][264] @0 (33792),
//           W2 double buffer @33792 + buf*36864 (chunks of K=64) -> 107520
//   epi2  : X2 fp32 [64][264] @0 (67584) - aliases A2+buf0 after all mma reads
//   aux   : b1s @107520, b2s @108544, gids @109568 -> 109824 total
// ---------------------------------------------------------------------------
#define SA1    0
#define SW1    17408
#define SA2    0
#define SW2C   33792
#define SW2STR 36864
#define SX2    0
#define SO_B1S 107520
#define SO_B2S 108544
#define SO_GID 109568
#define NODE_SMEM_BYTES 109824

extern "C" __global__ void __launch_bounds__(256, 2)
node_kernel(const float* __restrict__ h, const int* __restrict__ graph_ids,
            const float* __restrict__ b1, const float* __restrict__ b2, int n_atoms)
{
    extern __shared__ unsigned char sm[];
    const uint32_t smb = smem_to_u32(sm);
    const int tid = threadIdx.x;
    const int w   = tid >> 5;
    const int l   = tid & 31;
    const int q   = l >> 2;
    const int m   = l & 3;
    const int wm  = w >> 2;            // 0..1  (M group, 32 rows)
    const int wn  = w & 3;             // 0..3  (N group, 64 cols)
    const int Rb  = wm * 32;
    const int Cb  = wn * 64;
    const int row0 = blockIdx.x * TILE;

    // ldmatrix per-lane address components
    const int aRow  = l & 15;
    const int aKoff = (l >> 4) * 8;
    const int bN    = (l >> 4) * 8 + (l & 7);
    const int bKoff = ((l >> 3) & 1) * 8;

    float* b1s = (float*)(sm + SO_B1S);
    float* b2s = (float*)(sm + SO_B2S);
    int*   gids = (int*)(sm + SO_GID);

    // ---- prefetch W1 image via cp.async ----
    {
        const char* p = (const char*)&d_W1h[0];
        #pragma unroll
        for (int it = 0; it < 17; it++) {
            int o = (tid + it * 256) * 16;
            cp16(smb + SW1 + o, p + o);
        }
        CP_COMMIT();
    }

    b1s[tid] = b1[tid];
    b2s[tid] = b2[tid];
    if (tid < TILE) {
        int r = row0 + tid;
        gids[tid] = (r < n_atoms) ? graph_ids[r] : -1;
    }

    // ---- A1: load h tile, round to fp16, [r][k] stride 136 halfs ----
    #pragma unroll 4
    for (int it = 0; it < 8; it++) {
        int idx = tid + it * 256;          // 64 rows x 32 float4
        int r = idx >> 5, c = (idx & 31) * 4;
        float4 v = make_float4(0.f, 0.f, 0.f, 0.f);
        if (row0 + r < n_atoms)
            v = *(const float4*)(h + (size_t)(row0 + r) * DIN + c);
        uint32_t off = (uint32_t)(r * 136 + c) * 2;
        *(uint2*)(sm + SA1 + off) = make_uint2(pack2h(v.x, v.y), pack2h(v.z, v.w));
    }
    CP_WAITN(0);
    __syncthreads();

    float acc[64];
    #pragma unroll
    for (int i = 0; i < 64; i++) acc[i] = 0.f;

    // ================= Layer 1: K=128, 8 k-steps =================
    {
        const uint32_t aBase = smb + SA1 + (uint32_t)(((Rb + aRow) * 136 + aKoff) * 2);
        const uint32_t bBase = smb + SW1 + (uint32_t)(((Cb + bN) * 136 + bKoff) * 2);
        #pragma unroll
        for (int ks = 0; ks < 8; ks++) {
            uint32_t aH[8];
            ldsm4(aH[0], aH[1], aH[2], aH[3], aBase + ks * 32);
            ldsm4(aH[4], aH[5], aH[6], aH[7], aBase + 16 * 272 + ks * 32);
            #pragma unroll
            for (int nfp = 0; nfp < 4; nfp++) {
                uint32_t b0a, b1a, b0b, b1b;
                ldsm4(b0a, b1a, b0b, b1b, bBase + nfp * 16 * 272 + ks * 32);
                #pragma unroll
                for (int mf = 0; mf < 2; mf++) {
                    mma_f16(acc + (mf * 8 + nfp * 2) * 4,
                            aH[mf*4], aH[mf*4+1], aH[mf*4+2], aH[mf*4+3], b0a, b1a);
                    mma_f16(acc + (mf * 8 + nfp * 2 + 1) * 4,
                            aH[mf*4], aH[mf*4+1], aH[mf*4+2], aH[mf*4+3], b0b, b1b);
                }
            }
        }
    }
    __syncthreads();   // layer-1 reads of A1/W1 done; A2 / W2 buffers may overwrite

    // ---- issue W2 chunks 0,1 ----
    #pragma unroll
    for (int cc = 0; cc < 2; cc++) {
        const char* p = (const char*)&d_W2h[cc][0];
        uint32_t dst = smb + SW2C + cc * SW2STR;
        #pragma unroll
        for (int it = 0; it < 9; it++) {
            int o = (tid + it * 256) * 16;
            cp16(dst + o, p + o);
        }
        CP_COMMIT();
    }

    // ===== Epilogue 1: bias+relu, round to fp16 -> A2 [r][c] stride 264 =====
    #pragma unroll
    for (int mf = 0; mf < 2; mf++) {
        #pragma unroll
        for (int nf = 0; nf < 8; nf++) {
            int idx = (mf * 8 + nf) * 4;
            int c = Cb + nf * 8 + m * 2;
            int R = Rb + mf * 16 + q;
            float v0 = fmaxf(acc[idx+0] + b1s[c],     0.f);
            float v1 = fmaxf(acc[idx+1] + b1s[c + 1], 0.f);
            float v2 = fmaxf(acc[idx+2] + b1s[c],     0.f);
            float v3 = fmaxf(acc[idx+3] + b1s[c + 1], 0.f);
            uint32_t off = (uint32_t)((R * 264 + c) * 2);
            sts32(smb + SA2 + off, pack2h(v0, v1));
            sts32(smb + SA2 + off + 4224, pack2h(v2, v3));   // row +8
            acc[idx+0] = 0.f; acc[idx+1] = 0.f; acc[idx+2] = 0.f; acc[idx+3] = 0.f;
        }
    }

    // ========== Layer 2: K=256 in 4 chunks of 64, double-buffered ==========
    {
        const uint32_t aBase2 = smb + SA2 + (uint32_t)(((Rb + aRow) * 264 + aKoff) * 2);
        const uint32_t bOff   = (uint32_t)(((Cb + bN) * 72 + bKoff) * 2);
        #pragma unroll
        for (int c = 0; c < 4; c++) {
            if (c < 3) CP_WAITN(1); else CP_WAITN(0);
            __syncthreads();   // chunk data + (c==0) A2 stores visible
            const uint32_t bBase = smb + SW2C + (c & 1) * SW2STR + bOff;
            #pragma unroll
            for (int kk = 0; kk < 4; kk++) {
                uint32_t aH[8];
                ldsm4(aH[0], aH[1], aH[2], aH[3], aBase2 + c * 128 + kk * 32);
                ldsm4(aH[4], aH[5], aH[6], aH[7], aBase2 + 16 * 528 + c * 128 + kk * 32);
                #pragma unroll
                for (int nfp = 0; nfp < 4; nfp++) {
                    uint32_t b0a, b1a, b0b, b1b;
                    ldsm4(b0a, b1a, b0b, b1b, bBase + nfp * 16 * 144 + kk * 32);
                    #pragma unroll
                    for (int mf = 0; mf < 2; mf++) {
                        mma_f16(acc + (mf * 8 + nfp * 2) * 4,
                                aH[mf*4], aH[mf*4+1], aH[mf*4+2], aH[mf*4+3], b0a, b1a);
                        mma_f16(acc + (mf * 8 + nfp * 2 + 1) * 4,
                                aH[mf*4], aH[mf*4+1], aH[mf*4+2], aH[mf*4+3], b0b, b1b);
                    }
                }
            }
            __syncthreads();   // buffer consumed by all warps before re-fill
            if (c < 2) {
                const char* p = (const char*)&d_W2h[c + 2][0];
                uint32_t dst = smb + SW2C + (c & 1) * SW2STR;
                #pragma unroll
                for (int it = 0; it < 9; it++) {
                    int o = (tid + it * 256) * 16;
                    cp16(dst + o, p + o);
                }
                CP_COMMIT();
            }
        }
    }

    // ===== Epilogue 2: bias+relu -> X2 fp32 [r][264] =====
    {
        float* X2 = (float*)(sm + SX2);
        #pragma unroll
        for (int mf = 0; mf < 2; mf++) {
            #pragma unroll
            for (int nf = 0; nf < 8; nf++) {
                int idx = (mf * 8 + nf) * 4;
                int c = Cb + nf * 8 + m * 2;
                int R = Rb + mf * 16 + q;
                X2[R * 264 + c]           = fmaxf(acc[idx+0] + b2s[c],     0.f);
                X2[R * 264 + c + 1]       = fmaxf(acc[idx+1] + b2s[c + 1], 0.f);
                X2[(R + 8) * 264 + c]     = fmaxf(acc[idx+2] + b2s[c],     0.f);
                X2[(R + 8) * 264 + c + 1] = fmaxf(acc[idx+3] + b2s[c + 1], 0.f);
            }
        }
    }
    __syncthreads();

    // ===== Block-local segmented sum over sorted gids, then atomics =====
    {
        const int col = tid;
        const float* X2 = (const float*)(sm + SX2);
        int cur = -1;
        float s = 0.f;
        #pragma unroll 8
        for (int r = 0; r < TILE; r++) {
            int g = gids[r];
            if (g != cur) {
                if (cur >= 0) atomicAdd(&d_pooled[(size_t)cur * DH + col], s);
                cur = g;
                s = 0.f;
            }
            if (g >= 0) s += X2[r * 264 + col];
        }
        if (cur >= 0) atomicAdd(&d_pooled[(size_t)cur * DH + col], s);
    }
}

// ---------------------------------------------------------------------------
// Kernel 2: graph MLP, fp16 mma + ldmatrix, 64-graph tile (313 blocks).
// 256 threads (8 warps, 2M x 4N, 32x64 per-warp tile).
// smem: A[64][264] @0 (33792), Wg chunk0 @33792, chunk1 @103424 (->173056),
//       bg1s @173056, wsv @174080, rs @175104 (64x4 f32) -> 176128
// ---------------------------------------------------------------------------
#define GA     0
#define GW     33792
#define GWSTR  69632
#define GSO_BG1 173056
#define GSO_WS  174080
#define GSO_RS  175104
#define GRAPH_SMEM_BYTES 176128

extern "C" __global__ void __launch_bounds__(256, 1)
graph_kernel(const float* __restrict__ bg1, const float* __restrict__ Wg2,
             const float* __restrict__ bg2, float* __restrict__ out, int num_graphs)
{
    extern __shared__ unsigned char sm[];
    const uint32_t smb = smem_to_u32(sm);
    const int tid = threadIdx.x;
    const int l   = tid & 31;
    const int q   = l >> 2;
    const int m   = l & 3;
    const int w   = tid >> 5;
    const int wm  = w >> 2;            // 0..1  (32 rows)
    const int wn  = w & 3;             // 0..3  (64 cols)
    const int Rb  = wm * 32;
    const int Cb  = wn * 64;
    const int g0  = blockIdx.x * TILE;

    const int aRow  = l & 15;
    const int aKoff = (l >> 4) * 8;
    const int bN    = (l >> 4) * 8 + (l & 7);
    const int bKoff = ((l >> 3) & 1) * 8;

    float* bg1s = (float*)(sm + GSO_BG1);
    float* wsv  = (float*)(sm + GSO_WS);
    float* rs   = (float*)(sm + GSO_RS);

    // prefetch Wg1 chunks 0,1
    #pragma unroll
    for (int cc = 0; cc < 2; cc++) {
        const char* p = (const char*)&d_Wg1h[cc][0];
        uint32_t dst = smb + GW + cc * GWSTR;
        #pragma unroll
        for (int it = 0; it < 17; it++) {
            int o = (tid + it * 256) * 16;
            cp16(dst + o, p + o);
        }
        CP_COMMIT();
    }

    bg1s[tid] = bg1[tid];
    wsv[tid]  = Wg2[tid];

    // ---- A: load pooled tile, round to fp16, [r][c] stride 264 halfs ----
    #pragma unroll 4
    for (int it = 0; it < 16; it++) {
        int idx = tid + it * 256;          // 64 rows x 64 float4
        int r = idx >> 6, c = (idx & 63) * 4;
        float4 v = make_float4(0.f, 0.f, 0.f, 0.f);
        if (g0 + r < num_graphs)
            v = *(const float4*)(d_pooled + (size_t)(g0 + r) * DH + c);
        uint32_t off = (uint32_t)(r * 264 + c) * 2;
        *(uint2*)(sm + GA + off) = make_uint2(pack2h(v.x, v.y), pack2h(v.z, v.w));
    }

    float acc[64];
    #pragma unroll
    for (int i = 0; i < 64; i++) acc[i] = 0.f;

    // ======== GEMM: K=256 in 2 halves of 128 ========
    {
        const uint32_t aBase = smb + GA + (uint32_t)(((Rb + aRow) * 264 + aKoff) * 2);
        #pragma unroll
        for (int half = 0; half < 2; half++) {
            if (half == 0) CP_WAITN(1); else CP_WAITN(0);
            __syncthreads();
            const uint32_t bBase = smb + GW + half * GWSTR
                                 + (uint32_t)(((Cb + bN) * 136 + bKoff) * 2);
            #pragma unroll
            for (int kk = 0; kk < 8; kk++) {
                uint32_t aH[8];
                ldsm4(aH[0], aH[1], aH[2], aH[3], aBase + half * 256 + kk * 32);
                ldsm4(aH[4], aH[5], aH[6], aH[7], aBase + 16 * 528 + half * 256 + kk * 32);
                #pragma unroll
                for (int nfp = 0; nfp < 4; nfp++) {
                    uint32_t b0a, b1a, b0b, b1b;
                    ldsm4(b0a, b1a, b0b, b1b, bBase + nfp * 16 * 272 + kk * 32);
                    #pragma unroll
                    for (int mf = 0; mf < 2; mf++) {
                        mma_f16(acc + (mf * 8 + nfp * 2) * 4,
                                aH[mf*4], aH[mf*4+1], aH[mf*4+2], aH[mf*4+3], b0a, b1a);
                        mma_f16(acc + (mf * 8 + nfp * 2 + 1) * 4,
                                aH[mf*4], aH[mf*4+1], aH[mf*4+2], aH[mf*4+3], b0b, b1b);
                    }
                }
            }
        }
    }

    // ===== Epilogue: relu + dot with Wg2, warp reduce, rowsum smem =====
    #pragma unroll
    for (int mf = 0; mf < 2; mf++) {
        float p0 = 0.f, p1 = 0.f;
        #pragma unroll
        for (int nf = 0; nf < 8; nf++) {
            int idx = (mf * 8 + nf) * 4;
            int c = Cb + nf * 8 + m * 2;
            float w0 = wsv[c], w1 = wsv[c + 1];
            p0 += fmaxf(acc[idx+0] + bg1s[c],     0.f) * w0
                + fmaxf(acc[idx+1] + bg1s[c + 1], 0.f) * w1;
            p1 += fmaxf(acc[idx+2] + bg1s[c],     0.f) * w0
                + fmaxf(acc[idx+3] + bg1s[c + 1], 0.f) * w1;
        }
        p0 += __shfl_xor_sync(0xffffffffu, p0, 1);
        p0 += __shfl_xor_sync(0xffffffffu, p0, 2);
        p1 += __shfl_xor_sync(0xffffffffu, p1, 1);
        p1 += __shfl_xor_sync(0xffffffffu, p1, 2);
        if (m == 0) {
            int R = Rb + mf * 16 + q;
            rs[R * 4 + wn]       = p0;
            rs[(R + 8) * 4 + wn] = p1;
        }
    }
    __syncthreads();
    if (tid < TILE) {
        int g = g0 + tid;
        if (g < num_graphs)
            out[g] = rs[tid * 4] + rs[tid * 4 + 1] + rs[tid * 4 + 2] + rs[tid * 4 + 3] + bg2[0];
    }
}

// ---------------------------------------------------------------------------
extern "C" void kernel_launch(void* const* d_in, const int* in_sizes, int n_in,
                              void* d_out, int out_size) {
    const float* h         = (const float*)d_in[0];
    const int*   graph_ids = (const int*)  d_in[1];
    const int base = (n_in >= 11) ? 3 : 2;   // skip num_graphs scalar slot if present
    const float* W1  = (const float*)d_in[base + 0];
    const float* b1  = (const float*)d_in[base + 1];
    const float* W2  = (const float*)d_in[base + 2];
    const float* b2  = (const float*)d_in[base + 3];
    const float* Wg1 = (const float*)d_in[base + 4];
    const float* bg1 = (const float*)d_in[base + 5];
    const float* Wg2 = (const float*)d_in[base + 6];
    const float* bg2 = (const float*)d_in[base + 7];
    float* out = (float*)d_out;

    const int n_atoms = in_sizes[0] / DIN;
    const int G       = out_size;            // D_OUT = 1

    static bool attrs_set = false;
    if (!attrs_set) {
        cudaFuncSetAttribute(node_kernel,
                             cudaFuncAttributeMaxDynamicSharedMemorySize, NODE_SMEM_BYTES);
        cudaFuncSetAttribute(graph_kernel,
                             cudaFuncAttributeMaxDynamicSharedMemorySize, GRAPH_SMEM_BYTES);
        attrs_set = true;
    }

    prep_kernel<<<(DIN * DH + 2 * DH * DH + 255) / 256, 256>>>(W1, W2, Wg1);
    zero_pooled_kernel<<<512, 256>>>(G * DH);

    int nblocks = (n_atoms + TILE - 1) / TILE;
    node_kernel<<<nblocks, 256, NODE_SMEM_BYTES>>>(h, graph_ids, b1, b2, n_atoms);

    int gblocks = (G + TILE - 1) / TILE;
    graph_kernel<<<gblocks, 256, GRAPH_SMEM_BYTES>>>(bg1, Wg2, bg2, out, G);
}